// round 8
// baseline (speedup 1.0000x reference)
#include <cuda_runtime.h>
#include <math_constants.h>

#define N_NODES 65536
#define N_EDGES 1048576
#define IN_F 128
#define HID 64

// ---------------- scratch (device globals; no allocation allowed) ----------
__device__ float g_h0[N_NODES * HID];   // 16 MB
__device__ float g_h1[N_NODES * HID];   // 16 MB
__device__ float g_rnA[N_NODES];        // 1/max(||h||, eps) ping
__device__ float g_rnB[N_NODES];        // pong
__device__ int   g_deg[N_NODES];        // zeroed by scanF each pass
__device__ int   g_off[N_NODES + 1];
__device__ int   g_cur[N_NODES];
__device__ int   g_bsum[256];           // chunk sums; zeroed by projscatter
__device__ int   g_csr[N_EDGES];        // src node id, grouped by dst

// ---------------- launch 1: histogram (per-node + per-chunk) ---------------
__global__ __launch_bounds__(256) void hist_kernel(
    const int* __restrict__ dst, int* __restrict__ deg, int* __restrict__ bsum)
{
    int i = blockIdx.x * 256 + threadIdx.x;
    int d = __ldg(dst + i);
    atomicAdd(deg + d, 1);
    atomicAdd(bsum + (d >> 8), 1);
}

// ---------------- launch 2: fused scan (block-local + chunk) + deg reset ---
__global__ __launch_bounds__(256) void scanF_kernel(
    const int* __restrict__ bsum, int* __restrict__ deg,
    int* __restrict__ off, int* __restrict__ cur)
{
    __shared__ int s[256];
    __shared__ int sb[256];
    int t = threadIdx.x;
    int b = blockIdx.x;
    int g = b * 256 + t;
    int d = deg[g];
    s[t]  = d;
    sb[t] = bsum[t];
    __syncthreads();
#pragma unroll
    for (int o = 1; o < 256; o <<= 1) {
        int v1 = (t >= o) ? s[t - o]  : 0;
        int v2 = (t >= o) ? sb[t - o] : 0;
        __syncthreads();
        s[t] += v1; sb[t] += v2;
        __syncthreads();
    }
    int excl_blk = sb[b] - bsum[b];           // exclusive chunk prefix
    int v = (s[t] - d) + excl_blk;            // global exclusive offset
    off[g] = v;
    cur[g] = v;
    deg[g] = 0;                               // reset for next graph replay
    if (g == 0) off[N_NODES] = N_EDGES;
}

// ---------------- launch 3: scatter + proj GEMM (fused) --------------------
// proj: 16 rows/block, float4 k-tiling, transposed+padded W1 tile in smem.
// thread (r8 = tid>>5 in 0..7, c = tid&31): rows {r8, r8+8}, cols {c, c+32}.
__global__ __launch_bounds__(256) void projscatter_kernel(
    const int* __restrict__ src, const int* __restrict__ dst,
    int* __restrict__ cur, int* __restrict__ csr, int* __restrict__ bsum,
    const float* __restrict__ feat, const float* __restrict__ W1,
    const float* __restrict__ b1, float* __restrict__ out,
    float* __restrict__ rn)
{
    __shared__ float sF[16][IN_F];        // 8 KB
    __shared__ float sWt[HID][132];       // 33.8 KB, pad 132 -> conflict-free
    int tid = threadIdx.x;

    // --- scatter: 1 edge per thread (grid 4096 * 256 = N_EDGES) ---
    {
        int e = blockIdx.x * 256 + tid;
        int p = atomicAdd(cur + __ldg(dst + e), 1);
        csr[p] = __ldg(src + e);
    }
    if (blockIdx.x == 0) bsum[tid] = 0;   // reset chunk sums for next replay

    // --- stage tiles ---
    int row0 = blockIdx.x * 16;
    for (int i = tid; i < 16 * IN_F; i += 256)
        sF[i >> 7][i & 127] = feat[row0 * IN_F + i];
    for (int i = tid; i < IN_F * HID; i += 256) {
        int k = i >> 6, j = i & 63;
        sWt[j][k] = W1[i];
    }
    __syncthreads();

    int r8 = tid >> 5, c = tid & 31;
    float bc0 = b1[c], bc1 = b1[c + 32];
    float a00 = bc0, a01 = bc1;           // row r8
    float a10 = bc0, a11 = bc1;           // row r8+8
#pragma unroll
    for (int k4 = 0; k4 < IN_F / 4; k4++) {
        float4 w0 = *(const float4*)&sWt[c     ][k4 * 4];
        float4 w1 = *(const float4*)&sWt[c + 32][k4 * 4];
        float4 f0 = *(const float4*)&sF[r8    ][k4 * 4];
        float4 f1 = *(const float4*)&sF[r8 + 8][k4 * 4];
        a00 = fmaf(f0.x, w0.x, a00); a00 = fmaf(f0.y, w0.y, a00);
        a00 = fmaf(f0.z, w0.z, a00); a00 = fmaf(f0.w, w0.w, a00);
        a01 = fmaf(f0.x, w1.x, a01); a01 = fmaf(f0.y, w1.y, a01);
        a01 = fmaf(f0.z, w1.z, a01); a01 = fmaf(f0.w, w1.w, a01);
        a10 = fmaf(f1.x, w0.x, a10); a10 = fmaf(f1.y, w0.y, a10);
        a10 = fmaf(f1.z, w0.z, a10); a10 = fmaf(f1.w, w0.w, a10);
        a11 = fmaf(f1.x, w1.x, a11); a11 = fmaf(f1.y, w1.y, a11);
        a11 = fmaf(f1.z, w1.z, a11); a11 = fmaf(f1.w, w1.w, a11);
    }
    a00 = fmaxf(a00, 0.0f); a01 = fmaxf(a01, 0.0f);
    a10 = fmaxf(a10, 0.0f); a11 = fmaxf(a11, 0.0f);
    out[(row0 + r8    ) * HID + c     ] = a00;
    out[(row0 + r8    ) * HID + c + 32] = a01;
    out[(row0 + r8 + 8) * HID + c     ] = a10;
    out[(row0 + r8 + 8) * HID + c + 32] = a11;
    // fused row norms: each warp (fixed r8) covers all 64 cols of its 2 rows
    float p0 = a00 * a00 + a01 * a01;
    float p1 = a10 * a10 + a11 * a11;
#pragma unroll
    for (int o = 16; o; o >>= 1) {
        p0 += __shfl_xor_sync(0xffffffffu, p0, o);
        p1 += __shfl_xor_sync(0xffffffffu, p1, o);
    }
    if (c == 0) {
        rn[row0 + r8    ] = 1.0f / fmaxf(sqrtf(p0), 1e-12f);
        rn[row0 + r8 + 8] = 1.0f / fmaxf(sqrtf(p1), 1e-12f);
    }
}

// ---------------- launches 4,5: fused AGNN layer ---------------------------
// quarter-warp layout: qtr = lane>>3 owns edge slot (j+qtr); sub = lane&7
// owns feature elems [sub*8, sub*8+8) as two float4s. 4 edges per step,
// 3-deep butterfly, 2-stage software pipeline on the gathers.
__global__ __launch_bounds__(256) void layer_kernel(
    const int* __restrict__ csr, const int* __restrict__ off,
    const float* __restrict__ h, const float* __restrict__ rn_in,
    const float* __restrict__ betas, int layer,
    float* __restrict__ out, float* __restrict__ rn_out)
{
    int node = (blockIdx.x * blockDim.x + threadIdx.x) >> 5;
    int lane = threadIdx.x & 31;
    int qtr  = lane >> 3;
    int sub  = lane & 7;
    const unsigned FULL = 0xffffffffu;

    int s0 = off[node], s1 = off[node + 1];
    float beta = __ldg(betas + layer);
    float B = fabsf(beta);                        // analytic max of beta*cos
    const float* hq = h + node * HID + sub * 8;
    float4 qlo = *(const float4*)hq;
    float4 qhi = *(const float4*)(hq + 4);
    float qs = beta * rn_in[node];
    qlo.x *= qs; qlo.y *= qs; qlo.z *= qs; qlo.w *= qs;
    qhi.x *= qs; qhi.y *= qs; qhi.z *= qs; qhi.w *= qs;

    float ss = 0.0f;
    float4 alo = make_float4(0.f, 0.f, 0.f, 0.f);
    float4 ahi = make_float4(0.f, 0.f, 0.f, 0.f);

    for (int base = s0; base < s1; base += 32) {
        int inb = (base + lane < s1);
        int idx = inb ? __ldg(csr + base + lane) : 0;
        float rnl = inb ? rn_in[idx] : 0.0f;
        int cnt = min(32, s1 - base);
        // prefetch first quad
        int   sn = __shfl_sync(FULL, idx, qtr);
        float rs = __shfl_sync(FULL, rnl, qtr);
        const float* pa = h + sn * HID + sub * 8;
        float4 lo = *(const float4*)pa;
        float4 hi = *(const float4*)(pa + 4);
        for (int j = 0; j < cnt; j += 4) {
            // prefetch next quad (wrapped slot; discarded at tail)
            int nslot = (j + 4 + qtr) & 31;
            int   sn2 = __shfl_sync(FULL, idx, nslot);
            float rs2 = __shfl_sync(FULL, rnl, nslot);
            const float* pb = h + sn2 * HID + sub * 8;
            float4 lo2 = *(const float4*)pb;
            float4 hi2 = *(const float4*)(pb + 4);
            // process current
            float dt = qlo.x*lo.x + qlo.y*lo.y + qlo.z*lo.z + qlo.w*lo.w
                     + qhi.x*hi.x + qhi.y*hi.y + qhi.z*hi.z + qhi.w*hi.w;
            dt += __shfl_xor_sync(FULL, dt, 1);
            dt += __shfl_xor_sync(FULL, dt, 2);
            dt += __shfl_xor_sync(FULL, dt, 4);
            float w = (j + qtr < cnt) ? __expf(fmaf(dt, rs, -B)) : 0.0f;
            ss += w;
            alo.x = fmaf(w, lo.x, alo.x); alo.y = fmaf(w, lo.y, alo.y);
            alo.z = fmaf(w, lo.z, alo.z); alo.w = fmaf(w, lo.w, alo.w);
            ahi.x = fmaf(w, hi.x, ahi.x); ahi.y = fmaf(w, hi.y, ahi.y);
            ahi.z = fmaf(w, hi.z, ahi.z); ahi.w = fmaf(w, hi.w, ahi.w);
            lo = lo2; hi = hi2; rs = rs2;
        }
    }
    // combine the 4 quarters (lanes with equal sub end up identical)
    alo.x += __shfl_xor_sync(FULL, alo.x, 8);  alo.x += __shfl_xor_sync(FULL, alo.x, 16);
    alo.y += __shfl_xor_sync(FULL, alo.y, 8);  alo.y += __shfl_xor_sync(FULL, alo.y, 16);
    alo.z += __shfl_xor_sync(FULL, alo.z, 8);  alo.z += __shfl_xor_sync(FULL, alo.z, 16);
    alo.w += __shfl_xor_sync(FULL, alo.w, 8);  alo.w += __shfl_xor_sync(FULL, alo.w, 16);
    ahi.x += __shfl_xor_sync(FULL, ahi.x, 8);  ahi.x += __shfl_xor_sync(FULL, ahi.x, 16);
    ahi.y += __shfl_xor_sync(FULL, ahi.y, 8);  ahi.y += __shfl_xor_sync(FULL, ahi.y, 16);
    ahi.z += __shfl_xor_sync(FULL, ahi.z, 8);  ahi.z += __shfl_xor_sync(FULL, ahi.z, 16);
    ahi.w += __shfl_xor_sync(FULL, ahi.w, 8);  ahi.w += __shfl_xor_sync(FULL, ahi.w, 16);
    ss += __shfl_xor_sync(FULL, ss, 8);
    ss += __shfl_xor_sync(FULL, ss, 16);
    float inv = (s1 > s0) ? __frcp_rn(ss) : 0.0f;
    alo.x *= inv; alo.y *= inv; alo.z *= inv; alo.w *= inv;
    ahi.x *= inv; ahi.y *= inv; ahi.z *= inv; ahi.w *= inv;
    float ns = alo.x*alo.x + alo.y*alo.y + alo.z*alo.z + alo.w*alo.w
             + ahi.x*ahi.x + ahi.y*ahi.y + ahi.z*ahi.z + ahi.w*ahi.w;
    ns += __shfl_xor_sync(FULL, ns, 1);
    ns += __shfl_xor_sync(FULL, ns, 2);
    ns += __shfl_xor_sync(FULL, ns, 4);
    if (qtr == 0) {
        float* po = out + node * HID + sub * 8;
        *(float4*)po       = alo;
        *(float4*)(po + 4) = ahi;
        if (sub == 0)
            rn_out[node] = 1.0f / fmaxf(sqrtf(ns), 1e-12f);
    }
}

// ---------------- launch 6: cls = h @ W2 + b2 (same tiling, 32 rows) -------
__global__ __launch_bounds__(256) void cls_kernel(
    const float* __restrict__ h, const float* __restrict__ W2,
    const float* __restrict__ b2, float* __restrict__ out)
{
    __shared__ float sF[32][HID];         // 8 KB
    __shared__ float sWt[HID][68];        // 17.4 KB, pad 68
    int tid = threadIdx.x;
    int row0 = blockIdx.x * 32;
    for (int i = tid; i < 32 * HID; i += 256)
        sF[i >> 6][i & 63] = h[row0 * HID + i];
    for (int i = tid; i < HID * HID; i += 256) {
        int k = i >> 6, j = i & 63;
        sWt[j][k] = W2[i];
    }
    __syncthreads();

    int r8 = tid >> 5, c = tid & 31;
    float bc0 = b2[c], bc1 = b2[c + 32];
    float a00 = bc0, a01 = bc1, a10 = bc0, a11 = bc1;
    float a20 = bc0, a21 = bc1, a30 = bc0, a31 = bc1;
#pragma unroll
    for (int k4 = 0; k4 < HID / 4; k4++) {
        float4 w0 = *(const float4*)&sWt[c     ][k4 * 4];
        float4 w1 = *(const float4*)&sWt[c + 32][k4 * 4];
        float4 f0 = *(const float4*)&sF[r8     ][k4 * 4];
        float4 f1 = *(const float4*)&sF[r8 +  8][k4 * 4];
        float4 f2 = *(const float4*)&sF[r8 + 16][k4 * 4];
        float4 f3 = *(const float4*)&sF[r8 + 24][k4 * 4];
        a00 = fmaf(f0.x, w0.x, a00); a00 = fmaf(f0.y, w0.y, a00);
        a00 = fmaf(f0.z, w0.z, a00); a00 = fmaf(f0.w, w0.w, a00);
        a01 = fmaf(f0.x, w1.x, a01); a01 = fmaf(f0.y, w1.y, a01);
        a01 = fmaf(f0.z, w1.z, a01); a01 = fmaf(f0.w, w1.w, a01);
        a10 = fmaf(f1.x, w0.x, a10); a10 = fmaf(f1.y, w0.y, a10);
        a10 = fmaf(f1.z, w0.z, a10); a10 = fmaf(f1.w, w0.w, a10);
        a11 = fmaf(f1.x, w1.x, a11); a11 = fmaf(f1.y, w1.y, a11);
        a11 = fmaf(f1.z, w1.z, a11); a11 = fmaf(f1.w, w1.w, a11);
        a20 = fmaf(f2.x, w0.x, a20); a20 = fmaf(f2.y, w0.y, a20);
        a20 = fmaf(f2.z, w0.z, a20); a20 = fmaf(f2.w, w0.w, a20);
        a21 = fmaf(f2.x, w1.x, a21); a21 = fmaf(f2.y, w1.y, a21);
        a21 = fmaf(f2.z, w1.z, a21); a21 = fmaf(f2.w, w1.w, a21);
        a30 = fmaf(f3.x, w0.x, a30); a30 = fmaf(f3.y, w0.y, a30);
        a30 = fmaf(f3.z, w0.z, a30); a30 = fmaf(f3.w, w0.w, a30);
        a31 = fmaf(f3.x, w1.x, a31); a31 = fmaf(f3.y, w1.y, a31);
        a31 = fmaf(f3.z, w1.z, a31); a31 = fmaf(f3.w, w1.w, a31);
    }
    out[(row0 + r8     ) * HID + c     ] = a00;
    out[(row0 + r8     ) * HID + c + 32] = a01;
    out[(row0 + r8 +  8) * HID + c     ] = a10;
    out[(row0 + r8 +  8) * HID + c + 32] = a11;
    out[(row0 + r8 + 16) * HID + c     ] = a20;
    out[(row0 + r8 + 16) * HID + c + 32] = a21;
    out[(row0 + r8 + 24) * HID + c     ] = a30;
    out[(row0 + r8 + 24) * HID + c + 32] = a31;
}

// ---------------------------------------------------------------------------
extern "C" void kernel_launch(void* const* d_in, const int* in_sizes, int n_in,
                              void* d_out, int out_size)
{
    const float* feat  = (const float*)d_in[0];
    const int*   src   = (const int*)  d_in[1];
    const int*   dst   = (const int*)  d_in[2];
    const float* W1    = (const float*)d_in[3];
    const float* b1    = (const float*)d_in[4];
    const float* W2    = (const float*)d_in[5];
    const float* b2    = (const float*)d_in[6];
    const float* betas = (const float*)d_in[7];

    float *h0, *h1, *rnA, *rnB; int *deg, *off, *cur, *bsum, *csr;
    cudaGetSymbolAddress((void**)&h0,   g_h0);
    cudaGetSymbolAddress((void**)&h1,   g_h1);
    cudaGetSymbolAddress((void**)&rnA,  g_rnA);
    cudaGetSymbolAddress((void**)&rnB,  g_rnB);
    cudaGetSymbolAddress((void**)&deg,  g_deg);
    cudaGetSymbolAddress((void**)&off,  g_off);
    cudaGetSymbolAddress((void**)&cur,  g_cur);
    cudaGetSymbolAddress((void**)&bsum, g_bsum);
    cudaGetSymbolAddress((void**)&csr,  g_csr);

    hist_kernel<<<N_EDGES / 256, 256>>>(dst, deg, bsum);
    scanF_kernel<<<N_NODES / 256, 256>>>(bsum, deg, off, cur);
    projscatter_kernel<<<N_NODES / 16, 256>>>(src, dst, cur, csr, bsum,
                                              feat, W1, b1, h0, rnA);
    layer_kernel<<<N_NODES * 32 / 256, 256>>>(csr, off, h0, rnA, betas, 0, h1, rnB);
    layer_kernel<<<N_NODES * 32 / 256, 256>>>(csr, off, h1, rnB, betas, 1, h0, rnA);
    cls_kernel<<<N_NODES / 32, 256>>>(h0, W2, b2, (float*)d_out);
}

// round 9
// speedup vs baseline: 2.1492x; 2.1492x over previous
#include <cuda_runtime.h>
#include <cuda_fp16.h>
#include <math_constants.h>

#define N_NODES 65536
#define N_EDGES 1048576
#define IN_F 128
#define HID 64

// ---------------- scratch (device globals; no allocation allowed) ----------
__device__ __half g_h0[N_NODES * HID];  // 8 MB, fp16 node features ping
__device__ __half g_h1[N_NODES * HID];  // 8 MB, pong
__device__ float  g_rnA[N_NODES];       // 1/max(||h||, eps) ping (fp32)
__device__ float  g_rnB[N_NODES];       // pong
__device__ int    g_deg[N_NODES];       // zeroed by scan1 each pass
__device__ int    g_off[N_NODES + 1];
__device__ int    g_cur[N_NODES];
__device__ int    g_bsum[256];
__device__ int    g_csr[N_EDGES];       // src node id, grouped by dst

// ---------------- CSR build (R6 structure — no hot-address atomics) --------
__global__ __launch_bounds__(256) void hist_kernel(
    const int* __restrict__ dst, int* __restrict__ deg) {
    int i = blockIdx.x * 256 + threadIdx.x;
    atomicAdd(deg + __ldg(dst + i), 1);
}

// block-local scan; writes block sum; resets deg for the next replay
__global__ __launch_bounds__(256) void scan1_kernel(
    int* __restrict__ deg, int* __restrict__ off, int* __restrict__ bsum) {
    __shared__ int s[256];
    int t = threadIdx.x;
    int g = blockIdx.x * 256 + t;
    int d = deg[g];
    deg[g] = 0;                        // reset for next graph replay
    s[t] = d;
    __syncthreads();
#pragma unroll
    for (int o = 1; o < 256; o <<= 1) {
        int v = (t >= o) ? s[t - o] : 0;
        __syncthreads();
        s[t] += v;
        __syncthreads();
    }
    off[g] = s[t] - d;
    if (t == 255) bsum[blockIdx.x] = s[255];
}

// every block redundantly scans the 256 block sums, then applies offsets
__global__ __launch_bounds__(256) void scan23_kernel(
    int* __restrict__ off, const int* __restrict__ bsum, int* __restrict__ cur) {
    __shared__ int s[256];
    int t = threadIdx.x;
    int d = bsum[t];
    s[t] = d;
    __syncthreads();
#pragma unroll
    for (int o = 1; o < 256; o <<= 1) {
        int v = (t >= o) ? s[t - o] : 0;
        __syncthreads();
        s[t] += v;
        __syncthreads();
    }
    __syncthreads();
    int i = blockIdx.x * 256 + t;
    int b = i >> 8;
    int excl = s[b] - bsum[b];
    int v = off[i] + excl;
    off[i] = v;
    cur[i] = v;
    if (i == 0) off[N_NODES] = N_EDGES;
}

__global__ __launch_bounds__(256) void scatter_kernel(
    const int* __restrict__ src, const int* __restrict__ dst,
    int* __restrict__ cur, int* __restrict__ csr) {
    int i = blockIdx.x * 256 + threadIdx.x;
    int p = atomicAdd(cur + __ldg(dst + i), 1);
    csr[p] = __ldg(src + i);
}

// ---------------- fp16 pack/unpack helpers ---------------------------------
__device__ __forceinline__ void unpack8(uint4 r, float* f) {
    float2 t;
    t = __half22float2(*reinterpret_cast<__half2*>(&r.x)); f[0] = t.x; f[1] = t.y;
    t = __half22float2(*reinterpret_cast<__half2*>(&r.y)); f[2] = t.x; f[3] = t.y;
    t = __half22float2(*reinterpret_cast<__half2*>(&r.z)); f[4] = t.x; f[5] = t.y;
    t = __half22float2(*reinterpret_cast<__half2*>(&r.w)); f[6] = t.x; f[7] = t.y;
}
__device__ __forceinline__ uint4 pack8(const float* f) {
    uint4 r;
    __half2 p;
    p = __floats2half2_rn(f[0], f[1]); r.x = *reinterpret_cast<unsigned*>(&p);
    p = __floats2half2_rn(f[2], f[3]); r.y = *reinterpret_cast<unsigned*>(&p);
    p = __floats2half2_rn(f[4], f[5]); r.z = *reinterpret_cast<unsigned*>(&p);
    p = __floats2half2_rn(f[6], f[7]); r.w = *reinterpret_cast<unsigned*>(&p);
    return r;
}

// ---------------- proj: h = relu(features @ W1 + b1) -> fp16 + fused norms -
__global__ __launch_bounds__(256) void proj_kernel(
    const float* __restrict__ feat, const float* __restrict__ W1,
    const float* __restrict__ b1, __half* __restrict__ out,
    float* __restrict__ rn)
{
    __shared__ float sF[16][IN_F];        // 8 KB
    __shared__ float sWt[HID][132];       // 33.8 KB, padded
    int tid = threadIdx.x;
    int row0 = blockIdx.x * 16;
    for (int i = tid; i < 16 * IN_F; i += 256)
        sF[i >> 7][i & 127] = feat[row0 * IN_F + i];
    for (int i = tid; i < IN_F * HID; i += 256) {
        int k = i >> 6, j = i & 63;
        sWt[j][k] = W1[i];
    }
    __syncthreads();

    int r8 = tid >> 5, c = tid & 31;
    float bc0 = b1[c], bc1 = b1[c + 32];
    float a00 = bc0, a01 = bc1;
    float a10 = bc0, a11 = bc1;
#pragma unroll
    for (int k4 = 0; k4 < IN_F / 4; k4++) {
        float4 w0 = *(const float4*)&sWt[c     ][k4 * 4];
        float4 w1 = *(const float4*)&sWt[c + 32][k4 * 4];
        float4 f0 = *(const float4*)&sF[r8    ][k4 * 4];
        float4 f1 = *(const float4*)&sF[r8 + 8][k4 * 4];
        a00 = fmaf(f0.x, w0.x, a00); a00 = fmaf(f0.y, w0.y, a00);
        a00 = fmaf(f0.z, w0.z, a00); a00 = fmaf(f0.w, w0.w, a00);
        a01 = fmaf(f0.x, w1.x, a01); a01 = fmaf(f0.y, w1.y, a01);
        a01 = fmaf(f0.z, w1.z, a01); a01 = fmaf(f0.w, w1.w, a01);
        a10 = fmaf(f1.x, w0.x, a10); a10 = fmaf(f1.y, w0.y, a10);
        a10 = fmaf(f1.z, w0.z, a10); a10 = fmaf(f1.w, w0.w, a10);
        a11 = fmaf(f1.x, w1.x, a11); a11 = fmaf(f1.y, w1.y, a11);
        a11 = fmaf(f1.z, w1.z, a11); a11 = fmaf(f1.w, w1.w, a11);
    }
    a00 = fmaxf(a00, 0.0f); a01 = fmaxf(a01, 0.0f);
    a10 = fmaxf(a10, 0.0f); a11 = fmaxf(a11, 0.0f);
    out[(row0 + r8    ) * HID + c     ] = __float2half_rn(a00);
    out[(row0 + r8    ) * HID + c + 32] = __float2half_rn(a01);
    out[(row0 + r8 + 8) * HID + c     ] = __float2half_rn(a10);
    out[(row0 + r8 + 8) * HID + c + 32] = __float2half_rn(a11);
    float p0 = a00 * a00 + a01 * a01;
    float p1 = a10 * a10 + a11 * a11;
#pragma unroll
    for (int o = 16; o; o >>= 1) {
        p0 += __shfl_xor_sync(0xffffffffu, p0, o);
        p1 += __shfl_xor_sync(0xffffffffu, p1, o);
    }
    if (c == 0) {
        rn[row0 + r8    ] = 1.0f / fmaxf(sqrtf(p0), 1e-12f);
        rn[row0 + r8 + 8] = 1.0f / fmaxf(sqrtf(p1), 1e-12f);
    }
}

// ---------------- fused AGNN layer: warp/dst, fp16 gathers -----------------
// quarter-warp: qtr = lane>>3 owns edge slot (j+qtr); sub = lane&7 owns
// feature elems [sub*8, sub*8+8) as ONE uint4 (8 halfs = 16 B).
// A 64-dim fp16 row is exactly one 128B cache line -> 1 wavefront/edge.
__global__ __launch_bounds__(256) void layer_kernel(
    const int* __restrict__ csr, const int* __restrict__ off,
    const __half* __restrict__ hh, const float* __restrict__ rn_in,
    const float* __restrict__ betas, int layer,
    __half* __restrict__ out_h, float* __restrict__ rn_out)
{
    int node = (blockIdx.x * blockDim.x + threadIdx.x) >> 5;
    int lane = threadIdx.x & 31;
    int qtr  = lane >> 3;
    int sub  = lane & 7;
    const unsigned FULL = 0xffffffffu;

    int s0 = off[node], s1 = off[node + 1];
    float beta = __ldg(betas + layer);
    float B = fabsf(beta);                        // analytic max of beta*cos
    float q[8];
    {
        uint4 qraw = *(const uint4*)(hh + node * HID + sub * 8);
        unpack8(qraw, q);
        float qs = beta * rn_in[node];
#pragma unroll
        for (int i = 0; i < 8; i++) q[i] *= qs;
    }

    float ss = 0.0f;
    float acc[8] = {0.f, 0.f, 0.f, 0.f, 0.f, 0.f, 0.f, 0.f};

    for (int base = s0; base < s1; base += 32) {
        int inb = (base + lane < s1);
        int idx = inb ? __ldg(csr + base + lane) : 0;
        float rnl = inb ? rn_in[idx] : 0.0f;
        int cnt = min(32, s1 - base);
        // prefetch first quad
        int   sn = __shfl_sync(FULL, idx, qtr);
        float rs = __shfl_sync(FULL, rnl, qtr);
        uint4 raw = *(const uint4*)(hh + sn * HID + sub * 8);
        for (int j = 0; j < cnt; j += 4) {
            // prefetch next quad (wrapped slot; discarded at tail)
            int nslot = (j + 4 + qtr) & 31;
            int   sn2 = __shfl_sync(FULL, idx, nslot);
            float rs2 = __shfl_sync(FULL, rnl, nslot);
            uint4 raw2 = *(const uint4*)(hh + sn2 * HID + sub * 8);
            // process current
            float f[8];
            unpack8(raw, f);
            float dt = q[0]*f[0] + q[1]*f[1] + q[2]*f[2] + q[3]*f[3]
                     + q[4]*f[4] + q[5]*f[5] + q[6]*f[6] + q[7]*f[7];
            dt += __shfl_xor_sync(FULL, dt, 1);
            dt += __shfl_xor_sync(FULL, dt, 2);
            dt += __shfl_xor_sync(FULL, dt, 4);
            float w = (j + qtr < cnt) ? __expf(fmaf(dt, rs, -B)) : 0.0f;
            ss += w;
#pragma unroll
            for (int i = 0; i < 8; i++) acc[i] = fmaf(w, f[i], acc[i]);
            raw = raw2; rs = rs2;
        }
    }
    // combine the 4 quarters (lanes with equal sub end up identical)
#pragma unroll
    for (int i = 0; i < 8; i++) {
        acc[i] += __shfl_xor_sync(FULL, acc[i], 8);
        acc[i] += __shfl_xor_sync(FULL, acc[i], 16);
    }
    ss += __shfl_xor_sync(FULL, ss, 8);
    ss += __shfl_xor_sync(FULL, ss, 16);
    float inv = (s1 > s0) ? __frcp_rn(ss) : 0.0f;
    float ns = 0.0f;
#pragma unroll
    for (int i = 0; i < 8; i++) {
        acc[i] *= inv;
        ns = fmaf(acc[i], acc[i], ns);
    }
    ns += __shfl_xor_sync(FULL, ns, 1);
    ns += __shfl_xor_sync(FULL, ns, 2);
    ns += __shfl_xor_sync(FULL, ns, 4);
    if (qtr == 0) {
        *(uint4*)(out_h + node * HID + sub * 8) = pack8(acc);
        if (sub == 0)
            rn_out[node] = 1.0f / fmaxf(sqrtf(ns), 1e-12f);
    }
}

// ---------------- cls: out = h(fp16) @ W2 + b2, 32 rows/block --------------
__global__ __launch_bounds__(256) void cls_kernel(
    const __half* __restrict__ hh, const float* __restrict__ W2,
    const float* __restrict__ b2, float* __restrict__ out)
{
    __shared__ float sF[32][HID];         // 8 KB
    __shared__ float sWt[HID][68];        // 17.4 KB, padded
    int tid = threadIdx.x;
    int row0 = blockIdx.x * 32;
    for (int i = tid; i < 32 * HID; i += 256)
        sF[i >> 6][i & 63] = __half2float(hh[row0 * HID + i]);
    for (int i = tid; i < HID * HID; i += 256) {
        int k = i >> 6, j = i & 63;
        sWt[j][k] = W2[i];
    }
    __syncthreads();

    int r8 = tid >> 5, c = tid & 31;
    float bc0 = b2[c], bc1 = b2[c + 32];
    float a00 = bc0, a01 = bc1, a10 = bc0, a11 = bc1;
    float a20 = bc0, a21 = bc1, a30 = bc0, a31 = bc1;
#pragma unroll
    for (int k4 = 0; k4 < HID / 4; k4++) {
        float4 w0 = *(const float4*)&sWt[c     ][k4 * 4];
        float4 w1 = *(const float4*)&sWt[c + 32][k4 * 4];
        float4 f0 = *(const float4*)&sF[r8     ][k4 * 4];
        float4 f1 = *(const float4*)&sF[r8 +  8][k4 * 4];
        float4 f2 = *(const float4*)&sF[r8 + 16][k4 * 4];
        float4 f3 = *(const float4*)&sF[r8 + 24][k4 * 4];
        a00 = fmaf(f0.x, w0.x, a00); a00 = fmaf(f0.y, w0.y, a00);
        a00 = fmaf(f0.z, w0.z, a00); a00 = fmaf(f0.w, w0.w, a00);
        a01 = fmaf(f0.x, w1.x, a01); a01 = fmaf(f0.y, w1.y, a01);
        a01 = fmaf(f0.z, w1.z, a01); a01 = fmaf(f0.w, w1.w, a01);
        a10 = fmaf(f1.x, w0.x, a10); a10 = fmaf(f1.y, w0.y, a10);
        a10 = fmaf(f1.z, w0.z, a10); a10 = fmaf(f1.w, w0.w, a10);
        a11 = fmaf(f1.x, w1.x, a11); a11 = fmaf(f1.y, w1.y, a11);
        a11 = fmaf(f1.z, w1.z, a11); a11 = fmaf(f1.w, w1.w, a11);
        a20 = fmaf(f2.x, w0.x, a20); a20 = fmaf(f2.y, w0.y, a20);
        a20 = fmaf(f2.z, w0.z, a20); a20 = fmaf(f2.w, w0.w, a20);
        a21 = fmaf(f2.x, w1.x, a21); a21 = fmaf(f2.y, w1.y, a21);
        a21 = fmaf(f2.z, w1.z, a21); a21 = fmaf(f2.w, w1.w, a21);
        a30 = fmaf(f3.x, w0.x, a30); a30 = fmaf(f3.y, w0.y, a30);
        a30 = fmaf(f3.z, w0.z, a30); a30 = fmaf(f3.w, w0.w, a30);
        a31 = fmaf(f3.x, w1.x, a31); a31 = fmaf(f3.y, w1.y, a31);
        a31 = fmaf(f3.z, w1.z, a31); a31 = fmaf(f3.w, w1.w, a31);
    }
    out[(row0 + r8     ) * HID + c     ] = a00;
    out[(row0 + r8     ) * HID + c + 32] = a01;
    out[(row0 + r8 +  8) * HID + c     ] = a10;
    out[(row0 + r8 +  8) * HID + c + 32] = a11;
    out[(row0 + r8 + 16) * HID + c     ] = a20;
    out[(row0 + r8 + 16) * HID + c + 32] = a21;
    out[(row0 + r8 + 24) * HID + c     ] = a30;
    out[(row0 + r8 + 24) * HID + c + 32] = a31;
}

// ---------------------------------------------------------------------------
extern "C" void kernel_launch(void* const* d_in, const int* in_sizes, int n_in,
                              void* d_out, int out_size)
{
    const float* feat  = (const float*)d_in[0];
    const int*   src   = (const int*)  d_in[1];
    const int*   dst   = (const int*)  d_in[2];
    const float* W1    = (const float*)d_in[3];
    const float* b1    = (const float*)d_in[4];
    const float* W2    = (const float*)d_in[5];
    const float* b2    = (const float*)d_in[6];
    const float* betas = (const float*)d_in[7];

    __half *h0, *h1; float *rnA, *rnB; int *deg, *off, *cur, *bsum, *csr;
    cudaGetSymbolAddress((void**)&h0,   g_h0);
    cudaGetSymbolAddress((void**)&h1,   g_h1);
    cudaGetSymbolAddress((void**)&rnA,  g_rnA);
    cudaGetSymbolAddress((void**)&rnB,  g_rnB);
    cudaGetSymbolAddress((void**)&deg,  g_deg);
    cudaGetSymbolAddress((void**)&off,  g_off);
    cudaGetSymbolAddress((void**)&cur,  g_cur);
    cudaGetSymbolAddress((void**)&bsum, g_bsum);
    cudaGetSymbolAddress((void**)&csr,  g_csr);

    // CSR by destination (built once, reused by both layers)
    hist_kernel<<<N_EDGES / 256, 256>>>(dst, deg);
    scan1_kernel<<<N_NODES / 256, 256>>>(deg, off, bsum);
    scan23_kernel<<<N_NODES / 256, 256>>>(off, bsum, cur);
    scatter_kernel<<<N_EDGES / 256, 256>>>(src, dst, cur, csr);

    proj_kernel<<<N_NODES / 16, 256>>>(feat, W1, b1, h0, rnA);

    layer_kernel<<<N_NODES * 32 / 256, 256>>>(csr, off, h0, rnA, betas, 0, h1, rnB);
    layer_kernel<<<N_NODES * 32 / 256, 256>>>(csr, off, h1, rnB, betas, 1, h0, rnA);

    cls_kernel<<<N_NODES / 32, 256>>>(h0, W2, b2, (float*)d_out);
}

// round 10
// speedup vs baseline: 2.1878x; 1.0180x over previous
#include <cuda_runtime.h>
#include <cuda_fp16.h>
#include <math_constants.h>

#define N_NODES 65536
#define N_EDGES 1048576
#define IN_F 128
#define HID 64

// ---------------- scratch (device globals; no allocation allowed) ----------
__device__ __half g_h0[N_NODES * HID];  // 8 MB, fp16 node features ping
__device__ __half g_h1[N_NODES * HID];  // 8 MB, pong
__device__ float  g_rnA[N_NODES];       // 1/max(||h||, eps) ping (fp32)
__device__ float  g_rnB[N_NODES];       // pong
__device__ int    g_deg[N_NODES];       // zeroed by scan1 each pass
__device__ int    g_off[N_NODES + 1];
__device__ int    g_cur[N_NODES];
__device__ int    g_bsum[256];
__device__ int    g_csr[N_EDGES];       // src node id, grouped by dst

// ---------------- CSR build: 4 edges/thread for MLP ------------------------
__global__ __launch_bounds__(256) void hist_kernel(
    const int* __restrict__ dst, int* __restrict__ deg) {
    int i = blockIdx.x * 256 + threadIdx.x;
    int4 d = __ldg((const int4*)dst + i);
    atomicAdd(deg + d.x, 1);
    atomicAdd(deg + d.y, 1);
    atomicAdd(deg + d.z, 1);
    atomicAdd(deg + d.w, 1);
}

// block-local scan; writes block sum; resets deg for the next replay
__global__ __launch_bounds__(256) void scan1_kernel(
    int* __restrict__ deg, int* __restrict__ off, int* __restrict__ bsum) {
    __shared__ int s[256];
    int t = threadIdx.x;
    int g = blockIdx.x * 256 + t;
    int d = deg[g];
    deg[g] = 0;
    s[t] = d;
    __syncthreads();
#pragma unroll
    for (int o = 1; o < 256; o <<= 1) {
        int v = (t >= o) ? s[t - o] : 0;
        __syncthreads();
        s[t] += v;
        __syncthreads();
    }
    off[g] = s[t] - d;
    if (t == 255) bsum[blockIdx.x] = s[255];
}

// every block redundantly scans the 256 block sums, then applies offsets
__global__ __launch_bounds__(256) void scan23_kernel(
    int* __restrict__ off, const int* __restrict__ bsum, int* __restrict__ cur) {
    __shared__ int s[256];
    int t = threadIdx.x;
    int d = bsum[t];
    s[t] = d;
    __syncthreads();
#pragma unroll
    for (int o = 1; o < 256; o <<= 1) {
        int v = (t >= o) ? s[t - o] : 0;
        __syncthreads();
        s[t] += v;
        __syncthreads();
    }
    __syncthreads();
    int i = blockIdx.x * 256 + t;
    int b = i >> 8;
    int excl = s[b] - bsum[b];
    int v = off[i] + excl;
    off[i] = v;
    cur[i] = v;
    if (i == 0) off[N_NODES] = N_EDGES;
}

__global__ __launch_bounds__(256) void scatter_kernel(
    const int* __restrict__ src, const int* __restrict__ dst,
    int* __restrict__ cur, int* __restrict__ csr) {
    int i = blockIdx.x * 256 + threadIdx.x;
    int4 d = __ldg((const int4*)dst + i);
    int4 s = __ldg((const int4*)src + i);
    int p0 = atomicAdd(cur + d.x, 1);
    int p1 = atomicAdd(cur + d.y, 1);
    int p2 = atomicAdd(cur + d.z, 1);
    int p3 = atomicAdd(cur + d.w, 1);
    csr[p0] = s.x;
    csr[p1] = s.y;
    csr[p2] = s.z;
    csr[p3] = s.w;
}

// ---------------- fp16 pack/unpack helpers ---------------------------------
__device__ __forceinline__ void unpack8(uint4 r, float* f) {
    float2 t;
    t = __half22float2(*reinterpret_cast<__half2*>(&r.x)); f[0] = t.x; f[1] = t.y;
    t = __half22float2(*reinterpret_cast<__half2*>(&r.y)); f[2] = t.x; f[3] = t.y;
    t = __half22float2(*reinterpret_cast<__half2*>(&r.z)); f[4] = t.x; f[5] = t.y;
    t = __half22float2(*reinterpret_cast<__half2*>(&r.w)); f[6] = t.x; f[7] = t.y;
}
__device__ __forceinline__ uint4 pack8(const float* f) {
    uint4 r;
    __half2 p;
    p = __floats2half2_rn(f[0], f[1]); r.x = *reinterpret_cast<unsigned*>(&p);
    p = __floats2half2_rn(f[2], f[3]); r.y = *reinterpret_cast<unsigned*>(&p);
    p = __floats2half2_rn(f[4], f[5]); r.z = *reinterpret_cast<unsigned*>(&p);
    p = __floats2half2_rn(f[6], f[7]); r.w = *reinterpret_cast<unsigned*>(&p);
    return r;
}

// ---------------- proj: h = relu(features @ W1 + b1) -> fp16 + fused norms -
__global__ __launch_bounds__(256) void proj_kernel(
    const float* __restrict__ feat, const float* __restrict__ W1,
    const float* __restrict__ b1, __half* __restrict__ out,
    float* __restrict__ rn)
{
    __shared__ float sF[16][IN_F];        // 8 KB
    __shared__ float sWt[HID][132];       // 33.8 KB, padded
    int tid = threadIdx.x;
    int row0 = blockIdx.x * 16;
    for (int i = tid; i < 16 * IN_F; i += 256)
        sF[i >> 7][i & 127] = feat[row0 * IN_F + i];
    for (int i = tid; i < IN_F * HID; i += 256) {
        int k = i >> 6, j = i & 63;
        sWt[j][k] = W1[i];
    }
    __syncthreads();

    int r8 = tid >> 5, c = tid & 31;
    float bc0 = b1[c], bc1 = b1[c + 32];
    float a00 = bc0, a01 = bc1;
    float a10 = bc0, a11 = bc1;
#pragma unroll
    for (int k4 = 0; k4 < IN_F / 4; k4++) {
        float4 w0 = *(const float4*)&sWt[c     ][k4 * 4];
        float4 w1 = *(const float4*)&sWt[c + 32][k4 * 4];
        float4 f0 = *(const float4*)&sF[r8    ][k4 * 4];
        float4 f1 = *(const float4*)&sF[r8 + 8][k4 * 4];
        a00 = fmaf(f0.x, w0.x, a00); a00 = fmaf(f0.y, w0.y, a00);
        a00 = fmaf(f0.z, w0.z, a00); a00 = fmaf(f0.w, w0.w, a00);
        a01 = fmaf(f0.x, w1.x, a01); a01 = fmaf(f0.y, w1.y, a01);
        a01 = fmaf(f0.z, w1.z, a01); a01 = fmaf(f0.w, w1.w, a01);
        a10 = fmaf(f1.x, w0.x, a10); a10 = fmaf(f1.y, w0.y, a10);
        a10 = fmaf(f1.z, w0.z, a10); a10 = fmaf(f1.w, w0.w, a10);
        a11 = fmaf(f1.x, w1.x, a11); a11 = fmaf(f1.y, w1.y, a11);
        a11 = fmaf(f1.z, w1.z, a11); a11 = fmaf(f1.w, w1.w, a11);
    }
    a00 = fmaxf(a00, 0.0f); a01 = fmaxf(a01, 0.0f);
    a10 = fmaxf(a10, 0.0f); a11 = fmaxf(a11, 0.0f);
    out[(row0 + r8    ) * HID + c     ] = __float2half_rn(a00);
    out[(row0 + r8    ) * HID + c + 32] = __float2half_rn(a01);
    out[(row0 + r8 + 8) * HID + c     ] = __float2half_rn(a10);
    out[(row0 + r8 + 8) * HID + c + 32] = __float2half_rn(a11);
    float p0 = a00 * a00 + a01 * a01;
    float p1 = a10 * a10 + a11 * a11;
#pragma unroll
    for (int o = 16; o; o >>= 1) {
        p0 += __shfl_xor_sync(0xffffffffu, p0, o);
        p1 += __shfl_xor_sync(0xffffffffu, p1, o);
    }
    if (c == 0) {
        rn[row0 + r8    ] = 1.0f / fmaxf(sqrtf(p0), 1e-12f);
        rn[row0 + r8 + 8] = 1.0f / fmaxf(sqrtf(p1), 1e-12f);
    }
}

// ---------------- fused AGNN layer: warp/dst, depth-2 gather pipeline ------
// quarter-warp: qtr = lane>>3 owns edge slot (j+qtr); sub = lane&7 owns
// feature elems [sub*8, sub*8+8) as ONE uint4 (8 halfs, 128B line per row).
// Two gather buffers in flight -> ~2x memory-level parallelism per warp.
__global__ __launch_bounds__(256) void layer_kernel(
    const int* __restrict__ csr, const int* __restrict__ off,
    const __half* __restrict__ hh, const float* __restrict__ rn_in,
    const float* __restrict__ betas, int layer,
    __half* __restrict__ out_h, float* __restrict__ rn_out)
{
    int node = (blockIdx.x * blockDim.x + threadIdx.x) >> 5;
    int lane = threadIdx.x & 31;
    int qtr  = lane >> 3;
    int sub  = lane & 7;
    const unsigned FULL = 0xffffffffu;

    int s0 = off[node], s1 = off[node + 1];
    float beta = __ldg(betas + layer);
    float B = fabsf(beta);                        // analytic max of beta*cos
    float q[8];
    {
        uint4 qraw = *(const uint4*)(hh + node * HID + sub * 8);
        unpack8(qraw, q);
        float qs = beta * rn_in[node];
#pragma unroll
        for (int i = 0; i < 8; i++) q[i] *= qs;
    }

    float ss = 0.0f;
    float acc[8] = {0.f, 0.f, 0.f, 0.f, 0.f, 0.f, 0.f, 0.f};

    for (int base = s0; base < s1; base += 32) {
        int inb = (base + lane < s1);
        int idx = inb ? __ldg(csr + base + lane) : 0;
        float rnl = inb ? rn_in[idx] : 0.0f;
        int cnt = min(32, s1 - base);
        // prime two pipeline stages
        int   snA = __shfl_sync(FULL, idx, qtr);
        float rsA = __shfl_sync(FULL, rnl, qtr);
        uint4 rawA = *(const uint4*)(hh + snA * HID + sub * 8);
        int   snB = __shfl_sync(FULL, idx, (4 + qtr) & 31);
        float rsB = __shfl_sync(FULL, rnl, (4 + qtr) & 31);
        uint4 rawB = *(const uint4*)(hh + snB * HID + sub * 8);
        for (int j = 0; j < cnt; j += 4) {
            // prefetch two steps ahead (wrapped slot; discarded at tail)
            int nslot = (j + 8 + qtr) & 31;
            int   snC = __shfl_sync(FULL, idx, nslot);
            float rsC = __shfl_sync(FULL, rnl, nslot);
            uint4 rawC = *(const uint4*)(hh + snC * HID + sub * 8);
            // process stage A
            float f[8];
            unpack8(rawA, f);
            float dt = q[0]*f[0] + q[1]*f[1] + q[2]*f[2] + q[3]*f[3]
                     + q[4]*f[4] + q[5]*f[5] + q[6]*f[6] + q[7]*f[7];
            dt += __shfl_xor_sync(FULL, dt, 1);
            dt += __shfl_xor_sync(FULL, dt, 2);
            dt += __shfl_xor_sync(FULL, dt, 4);
            float w = (j + qtr < cnt) ? __expf(fmaf(dt, rsA, -B)) : 0.0f;
            ss += w;
#pragma unroll
            for (int i = 0; i < 8; i++) acc[i] = fmaf(w, f[i], acc[i]);
            // rotate pipeline
            rawA = rawB; rsA = rsB;
            rawB = rawC; rsB = rsC;
        }
    }
    // combine the 4 quarters (lanes with equal sub end up identical)
#pragma unroll
    for (int i = 0; i < 8; i++) {
        acc[i] += __shfl_xor_sync(FULL, acc[i], 8);
        acc[i] += __shfl_xor_sync(FULL, acc[i], 16);
    }
    ss += __shfl_xor_sync(FULL, ss, 8);
    ss += __shfl_xor_sync(FULL, ss, 16);
    float inv = (s1 > s0) ? __frcp_rn(ss) : 0.0f;
    float ns = 0.0f;
#pragma unroll
    for (int i = 0; i < 8; i++) {
        acc[i] *= inv;
        ns = fmaf(acc[i], acc[i], ns);
    }
    ns += __shfl_xor_sync(FULL, ns, 1);
    ns += __shfl_xor_sync(FULL, ns, 2);
    ns += __shfl_xor_sync(FULL, ns, 4);
    if (qtr == 0) {
        *(uint4*)(out_h + node * HID + sub * 8) = pack8(acc);
        if (sub == 0)
            rn_out[node] = 1.0f / fmaxf(sqrtf(ns), 1e-12f);
    }
}

// ---------------- cls: out = h(fp16) @ W2 + b2, 32 rows/block --------------
__global__ __launch_bounds__(256) void cls_kernel(
    const __half* __restrict__ hh, const float* __restrict__ W2,
    const float* __restrict__ b2, float* __restrict__ out)
{
    __shared__ float sF[32][HID];         // 8 KB
    __shared__ float sWt[HID][68];        // 17.4 KB, padded
    int tid = threadIdx.x;
    int row0 = blockIdx.x * 32;
    for (int i = tid; i < 32 * HID; i += 256)
        sF[i >> 6][i & 63] = __half2float(hh[row0 * HID + i]);
    for (int i = tid; i < HID * HID; i += 256) {
        int k = i >> 6, j = i & 63;
        sWt[j][k] = W2[i];
    }
    __syncthreads();

    int r8 = tid >> 5, c = tid & 31;
    float bc0 = b2[c], bc1 = b2[c + 32];
    float a00 = bc0, a01 = bc1, a10 = bc0, a11 = bc1;
    float a20 = bc0, a21 = bc1, a30 = bc0, a31 = bc1;
#pragma unroll
    for (int k4 = 0; k4 < HID / 4; k4++) {
        float4 w0 = *(const float4*)&sWt[c     ][k4 * 4];
        float4 w1 = *(const float4*)&sWt[c + 32][k4 * 4];
        float4 f0 = *(const float4*)&sF[r8     ][k4 * 4];
        float4 f1 = *(const float4*)&sF[r8 +  8][k4 * 4];
        float4 f2 = *(const float4*)&sF[r8 + 16][k4 * 4];
        float4 f3 = *(const float4*)&sF[r8 + 24][k4 * 4];
        a00 = fmaf(f0.x, w0.x, a00); a00 = fmaf(f0.y, w0.y, a00);
        a00 = fmaf(f0.z, w0.z, a00); a00 = fmaf(f0.w, w0.w, a00);
        a01 = fmaf(f0.x, w1.x, a01); a01 = fmaf(f0.y, w1.y, a01);
        a01 = fmaf(f0.z, w1.z, a01); a01 = fmaf(f0.w, w1.w, a01);
        a10 = fmaf(f1.x, w0.x, a10); a10 = fmaf(f1.y, w0.y, a10);
        a10 = fmaf(f1.z, w0.z, a10); a10 = fmaf(f1.w, w0.w, a10);
        a11 = fmaf(f1.x, w1.x, a11); a11 = fmaf(f1.y, w1.y, a11);
        a11 = fmaf(f1.z, w1.z, a11); a11 = fmaf(f1.w, w1.w, a11);
        a20 = fmaf(f2.x, w0.x, a20); a20 = fmaf(f2.y, w0.y, a20);
        a20 = fmaf(f2.z, w0.z, a20); a20 = fmaf(f2.w, w0.w, a20);
        a21 = fmaf(f2.x, w1.x, a21); a21 = fmaf(f2.y, w1.y, a21);
        a21 = fmaf(f2.z, w1.z, a21); a21 = fmaf(f2.w, w1.w, a21);
        a30 = fmaf(f3.x, w0.x, a30); a30 = fmaf(f3.y, w0.y, a30);
        a30 = fmaf(f3.z, w0.z, a30); a30 = fmaf(f3.w, w0.w, a30);
        a31 = fmaf(f3.x, w1.x, a31); a31 = fmaf(f3.y, w1.y, a31);
        a31 = fmaf(f3.z, w1.z, a31); a31 = fmaf(f3.w, w1.w, a31);
    }
    out[(row0 + r8     ) * HID + c     ] = a00;
    out[(row0 + r8     ) * HID + c + 32] = a01;
    out[(row0 + r8 +  8) * HID + c     ] = a10;
    out[(row0 + r8 +  8) * HID + c + 32] = a11;
    out[(row0 + r8 + 16) * HID + c     ] = a20;
    out[(row0 + r8 + 16) * HID + c + 32] = a21;
    out[(row0 + r8 + 24) * HID + c     ] = a30;
    out[(row0 + r8 + 24) * HID + c + 32] = a31;
}

// ---------------------------------------------------------------------------
extern "C" void kernel_launch(void* const* d_in, const int* in_sizes, int n_in,
                              void* d_out, int out_size)
{
    const float* feat  = (const float*)d_in[0];
    const int*   src   = (const int*)  d_in[1];
    const int*   dst   = (const int*)  d_in[2];
    const float* W1    = (const float*)d_in[3];
    const float* b1    = (const float*)d_in[4];
    const float* W2    = (const float*)d_in[5];
    const float* b2    = (const float*)d_in[6];
    const float* betas = (const float*)d_in[7];

    __half *h0, *h1; float *rnA, *rnB; int *deg, *off, *cur, *bsum, *csr;
    cudaGetSymbolAddress((void**)&h0,   g_h0);
    cudaGetSymbolAddress((void**)&h1,   g_h1);
    cudaGetSymbolAddress((void**)&rnA,  g_rnA);
    cudaGetSymbolAddress((void**)&rnB,  g_rnB);
    cudaGetSymbolAddress((void**)&deg,  g_deg);
    cudaGetSymbolAddress((void**)&off,  g_off);
    cudaGetSymbolAddress((void**)&cur,  g_cur);
    cudaGetSymbolAddress((void**)&bsum, g_bsum);
    cudaGetSymbolAddress((void**)&csr,  g_csr);

    // CSR by destination (built once, reused by both layers)
    hist_kernel<<<N_EDGES / 4 / 256, 256>>>(dst, deg);
    scan1_kernel<<<N_NODES / 256, 256>>>(deg, off, bsum);
    scan23_kernel<<<N_NODES / 256, 256>>>(off, bsum, cur);
    scatter_kernel<<<N_EDGES / 4 / 256, 256>>>(src, dst, cur, csr);

    proj_kernel<<<N_NODES / 16, 256>>>(feat, W1, b1, h0, rnA);

    layer_kernel<<<N_NODES * 32 / 256, 256>>>(csr, off, h0, rnA, betas, 0, h1, rnB);
    layer_kernel<<<N_NODES * 32 / 256, 256>>>(csr, off, h1, rnB, betas, 1, h0, rnA);

    cls_kernel<<<N_NODES / 32, 256>>>(h0, W2, b2, (float*)d_out);
}

// round 11
// speedup vs baseline: 2.1924x; 1.0021x over previous
#include <cuda_runtime.h>
#include <cuda_fp16.h>
#include <math_constants.h>

#define N_NODES 65536
#define N_EDGES 1048576
#define IN_F 128
#define HID 64

// ---------------- scratch (device globals; no allocation allowed) ----------
__device__ __half g_h0[N_NODES * HID];  // 8 MB, fp16 node features ping
__device__ __half g_h1[N_NODES * HID];  // 8 MB, pong
__device__ float  g_rnA[N_NODES];       // 1/max(||h||, eps) ping (fp32)
__device__ float  g_rnB[N_NODES];       // pong
__device__ int    g_deg[N_NODES];       // zeroed by scanF each pass
__device__ int    g_off[N_NODES + 1];
__device__ int    g_cur[N_NODES];
__device__ int    g_bsum[256];          // chunk sums; zeroed by projscatter
__device__ int    g_csr[N_EDGES];       // src node id, grouped by dst

// ---------------- launch 1: histogram (node deg + smem-staged chunk sums) --
__global__ __launch_bounds__(256) void hist_kernel(
    const int* __restrict__ dst, int* __restrict__ deg, int* __restrict__ bsum)
{
    __shared__ int sc[256];
    int t = threadIdx.x;
    sc[t] = 0;
    __syncthreads();
    int i = blockIdx.x * 256 + t;
    int4 d = __ldg((const int4*)dst + i);
    atomicAdd(deg + d.x, 1);
    atomicAdd(deg + d.y, 1);
    atomicAdd(deg + d.z, 1);
    atomicAdd(deg + d.w, 1);
    atomicAdd(sc + (d.x >> 8), 1);
    atomicAdd(sc + (d.y >> 8), 1);
    atomicAdd(sc + (d.z >> 8), 1);
    atomicAdd(sc + (d.w >> 8), 1);
    __syncthreads();
    int v = sc[t];
    if (v) atomicAdd(bsum + t, v);      // 256 spread addresses per block
}

// ---------------- launch 2: fused scan (block-local + chunk) + deg reset ---
__global__ __launch_bounds__(256) void scanF_kernel(
    const int* __restrict__ bsum, int* __restrict__ deg,
    int* __restrict__ off, int* __restrict__ cur)
{
    __shared__ int s[256];
    __shared__ int sb[256];
    int t = threadIdx.x;
    int b = blockIdx.x;
    int g = b * 256 + t;
    int d = deg[g];
    deg[g] = 0;                          // reset for next graph replay
    s[t]  = d;
    sb[t] = bsum[t];
    __syncthreads();
#pragma unroll
    for (int o = 1; o < 256; o <<= 1) {
        int v1 = (t >= o) ? s[t - o]  : 0;
        int v2 = (t >= o) ? sb[t - o] : 0;
        __syncthreads();
        s[t] += v1; sb[t] += v2;
        __syncthreads();
    }
    int excl_blk = sb[b] - bsum[b];      // exclusive chunk prefix
    int v = (s[t] - d) + excl_blk;       // global exclusive offset
    off[g] = v;
    cur[g] = v;
    if (g == 0) off[N_NODES] = N_EDGES;
}

// ---------------- launch 3: scatter + proj GEMM (fused, fp16 out) ----------
__global__ __launch_bounds__(256) void projscatter_kernel(
    const int* __restrict__ src, const int* __restrict__ dst,
    int* __restrict__ cur, int* __restrict__ csr, int* __restrict__ bsum,
    const float* __restrict__ feat, const float* __restrict__ W1,
    const float* __restrict__ b1, __half* __restrict__ out,
    float* __restrict__ rn)
{
    __shared__ float sF[16][IN_F];        // 8 KB
    __shared__ float sWt[HID][132];       // 33.8 KB, padded
    int tid = threadIdx.x;

    // --- scatter: 1 edge per thread (grid 4096 * 256 = N_EDGES) ---
    {
        int e = blockIdx.x * 256 + tid;
        int p = atomicAdd(cur + __ldg(dst + e), 1);
        csr[p] = __ldg(src + e);
    }
    if (blockIdx.x == 0) bsum[tid] = 0;   // reset chunk sums for next replay

    // --- proj tiles ---
    int row0 = blockIdx.x * 16;
    for (int i = tid; i < 16 * IN_F; i += 256)
        sF[i >> 7][i & 127] = feat[row0 * IN_F + i];
    for (int i = tid; i < IN_F * HID; i += 256) {
        int k = i >> 6, j = i & 63;
        sWt[j][k] = W1[i];
    }
    __syncthreads();

    int r8 = tid >> 5, c = tid & 31;
    float bc0 = b1[c], bc1 = b1[c + 32];
    float a00 = bc0, a01 = bc1;
    float a10 = bc0, a11 = bc1;
#pragma unroll
    for (int k4 = 0; k4 < IN_F / 4; k4++) {
        float4 w0 = *(const float4*)&sWt[c     ][k4 * 4];
        float4 w1 = *(const float4*)&sWt[c + 32][k4 * 4];
        float4 f0 = *(const float4*)&sF[r8    ][k4 * 4];
        float4 f1 = *(const float4*)&sF[r8 + 8][k4 * 4];
        a00 = fmaf(f0.x, w0.x, a00); a00 = fmaf(f0.y, w0.y, a00);
        a00 = fmaf(f0.z, w0.z, a00); a00 = fmaf(f0.w, w0.w, a00);
        a01 = fmaf(f0.x, w1.x, a01); a01 = fmaf(f0.y, w1.y, a01);
        a01 = fmaf(f0.z, w1.z, a01); a01 = fmaf(f0.w, w1.w, a01);
        a10 = fmaf(f1.x, w0.x, a10); a10 = fmaf(f1.y, w0.y, a10);
        a10 = fmaf(f1.z, w0.z, a10); a10 = fmaf(f1.w, w0.w, a10);
        a11 = fmaf(f1.x, w1.x, a11); a11 = fmaf(f1.y, w1.y, a11);
        a11 = fmaf(f1.z, w1.z, a11); a11 = fmaf(f1.w, w1.w, a11);
    }
    a00 = fmaxf(a00, 0.0f); a01 = fmaxf(a01, 0.0f);
    a10 = fmaxf(a10, 0.0f); a11 = fmaxf(a11, 0.0f);
    out[(row0 + r8    ) * HID + c     ] = __float2half_rn(a00);
    out[(row0 + r8    ) * HID + c + 32] = __float2half_rn(a01);
    out[(row0 + r8 + 8) * HID + c     ] = __float2half_rn(a10);
    out[(row0 + r8 + 8) * HID + c + 32] = __float2half_rn(a11);
    float p0 = a00 * a00 + a01 * a01;
    float p1 = a10 * a10 + a11 * a11;
#pragma unroll
    for (int o = 16; o; o >>= 1) {
        p0 += __shfl_xor_sync(0xffffffffu, p0, o);
        p1 += __shfl_xor_sync(0xffffffffu, p1, o);
    }
    if (c == 0) {
        rn[row0 + r8    ] = 1.0f / fmaxf(sqrtf(p0), 1e-12f);
        rn[row0 + r8 + 8] = 1.0f / fmaxf(sqrtf(p1), 1e-12f);
    }
}

// ---------------- fp16 pack/unpack helpers ---------------------------------
__device__ __forceinline__ void unpack8(uint4 r, float* f) {
    float2 t;
    t = __half22float2(*reinterpret_cast<__half2*>(&r.x)); f[0] = t.x; f[1] = t.y;
    t = __half22float2(*reinterpret_cast<__half2*>(&r.y)); f[2] = t.x; f[3] = t.y;
    t = __half22float2(*reinterpret_cast<__half2*>(&r.z)); f[4] = t.x; f[5] = t.y;
    t = __half22float2(*reinterpret_cast<__half2*>(&r.w)); f[6] = t.x; f[7] = t.y;
}
__device__ __forceinline__ uint4 pack8(const float* f) {
    uint4 r;
    __half2 p;
    p = __floats2half2_rn(f[0], f[1]); r.x = *reinterpret_cast<unsigned*>(&p);
    p = __floats2half2_rn(f[2], f[3]); r.y = *reinterpret_cast<unsigned*>(&p);
    p = __floats2half2_rn(f[4], f[5]); r.z = *reinterpret_cast<unsigned*>(&p);
    p = __floats2half2_rn(f[6], f[7]); r.w = *reinterpret_cast<unsigned*>(&p);
    return r;
}

// ---------------- launches 4,5: fused AGNN layer (fp16, depth-2) -----------
__global__ __launch_bounds__(256) void layer_kernel(
    const int* __restrict__ csr, const int* __restrict__ off,
    const __half* __restrict__ hh, const float* __restrict__ rn_in,
    const float* __restrict__ betas, int layer,
    __half* __restrict__ out_h, float* __restrict__ rn_out)
{
    int node = (blockIdx.x * blockDim.x + threadIdx.x) >> 5;
    int lane = threadIdx.x & 31;
    int qtr  = lane >> 3;
    int sub  = lane & 7;
    const unsigned FULL = 0xffffffffu;

    int s0 = off[node], s1 = off[node + 1];
    float beta = __ldg(betas + layer);
    float B = fabsf(beta);                        // analytic max of beta*cos
    float q[8];
    {
        uint4 qraw = *(const uint4*)(hh + node * HID + sub * 8);
        unpack8(qraw, q);
        float qs = beta * rn_in[node];
#pragma unroll
        for (int i = 0; i < 8; i++) q[i] *= qs;
    }

    float ss = 0.0f;
    float acc[8] = {0.f, 0.f, 0.f, 0.f, 0.f, 0.f, 0.f, 0.f};

    for (int base = s0; base < s1; base += 32) {
        int inb = (base + lane < s1);
        int idx = inb ? __ldg(csr + base + lane) : 0;
        float rnl = inb ? rn_in[idx] : 0.0f;
        int cnt = min(32, s1 - base);
        // prime two pipeline stages
        int   snA = __shfl_sync(FULL, idx, qtr);
        float rsA = __shfl_sync(FULL, rnl, qtr);
        uint4 rawA = *(const uint4*)(hh + snA * HID + sub * 8);
        int   snB = __shfl_sync(FULL, idx, (4 + qtr) & 31);
        float rsB = __shfl_sync(FULL, rnl, (4 + qtr) & 31);
        uint4 rawB = *(const uint4*)(hh + snB * HID + sub * 8);
        for (int j = 0; j < cnt; j += 4) {
            // prefetch two steps ahead (wrapped slot; discarded at tail)
            int nslot = (j + 8 + qtr) & 31;
            int   snC = __shfl_sync(FULL, idx, nslot);
            float rsC = __shfl_sync(FULL, rnl, nslot);
            uint4 rawC = *(const uint4*)(hh + snC * HID + sub * 8);
            // process stage A
            float f[8];
            unpack8(rawA, f);
            float dt = q[0]*f[0] + q[1]*f[1] + q[2]*f[2] + q[3]*f[3]
                     + q[4]*f[4] + q[5]*f[5] + q[6]*f[6] + q[7]*f[7];
            dt += __shfl_xor_sync(FULL, dt, 1);
            dt += __shfl_xor_sync(FULL, dt, 2);
            dt += __shfl_xor_sync(FULL, dt, 4);
            float w = (j + qtr < cnt) ? __expf(fmaf(dt, rsA, -B)) : 0.0f;
            ss += w;
#pragma unroll
            for (int i = 0; i < 8; i++) acc[i] = fmaf(w, f[i], acc[i]);
            // rotate pipeline
            rawA = rawB; rsA = rsB;
            rawB = rawC; rsB = rsC;
        }
    }
    // combine the 4 quarters
#pragma unroll
    for (int i = 0; i < 8; i++) {
        acc[i] += __shfl_xor_sync(FULL, acc[i], 8);
        acc[i] += __shfl_xor_sync(FULL, acc[i], 16);
    }
    ss += __shfl_xor_sync(FULL, ss, 8);
    ss += __shfl_xor_sync(FULL, ss, 16);
    float inv = (s1 > s0) ? __frcp_rn(ss) : 0.0f;
    float ns = 0.0f;
#pragma unroll
    for (int i = 0; i < 8; i++) {
        acc[i] *= inv;
        ns = fmaf(acc[i], acc[i], ns);
    }
    ns += __shfl_xor_sync(FULL, ns, 1);
    ns += __shfl_xor_sync(FULL, ns, 2);
    ns += __shfl_xor_sync(FULL, ns, 4);
    if (qtr == 0) {
        *(uint4*)(out_h + node * HID + sub * 8) = pack8(acc);
        if (sub == 0)
            rn_out[node] = 1.0f / fmaxf(sqrtf(ns), 1e-12f);
    }
}

// ---------------- launch 6: cls = h(fp16) @ W2 + b2, 32 rows/block ---------
__global__ __launch_bounds__(256) void cls_kernel(
    const __half* __restrict__ hh, const float* __restrict__ W2,
    const float* __restrict__ b2, float* __restrict__ out)
{
    __shared__ float sF[32][HID];         // 8 KB
    __shared__ float sWt[HID][68];        // 17.4 KB, padded
    int tid = threadIdx.x;
    int row0 = blockIdx.x * 32;
    for (int i = tid; i < 32 * HID; i += 256)
        sF[i >> 6][i & 63] = __half2float(hh[row0 * HID + i]);
    for (int i = tid; i < HID * HID; i += 256) {
        int k = i >> 6, j = i & 63;
        sWt[j][k] = W2[i];
    }
    __syncthreads();

    int r8 = tid >> 5, c = tid & 31;
    float bc0 = b2[c], bc1 = b2[c + 32];
    float a00 = bc0, a01 = bc1, a10 = bc0, a11 = bc1;
    float a20 = bc0, a21 = bc1, a30 = bc0, a31 = bc1;
#pragma unroll
    for (int k4 = 0; k4 < HID / 4; k4++) {
        float4 w0 = *(const float4*)&sWt[c     ][k4 * 4];
        float4 w1 = *(const float4*)&sWt[c + 32][k4 * 4];
        float4 f0 = *(const float4*)&sF[r8     ][k4 * 4];
        float4 f1 = *(const float4*)&sF[r8 +  8][k4 * 4];
        float4 f2 = *(const float4*)&sF[r8 + 16][k4 * 4];
        float4 f3 = *(const float4*)&sF[r8 + 24][k4 * 4];
        a00 = fmaf(f0.x, w0.x, a00); a00 = fmaf(f0.y, w0.y, a00);
        a00 = fmaf(f0.z, w0.z, a00); a00 = fmaf(f0.w, w0.w, a00);
        a01 = fmaf(f0.x, w1.x, a01); a01 = fmaf(f0.y, w1.y, a01);
        a01 = fmaf(f0.z, w1.z, a01); a01 = fmaf(f0.w, w1.w, a01);
        a10 = fmaf(f1.x, w0.x, a10); a10 = fmaf(f1.y, w0.y, a10);
        a10 = fmaf(f1.z, w0.z, a10); a10 = fmaf(f1.w, w0.w, a10);
        a11 = fmaf(f1.x, w1.x, a11); a11 = fmaf(f1.y, w1.y, a11);
        a11 = fmaf(f1.z, w1.z, a11); a11 = fmaf(f1.w, w1.w, a11);
        a20 = fmaf(f2.x, w0.x, a20); a20 = fmaf(f2.y, w0.y, a20);
        a20 = fmaf(f2.z, w0.z, a20); a20 = fmaf(f2.w, w0.w, a20);
        a21 = fmaf(f2.x, w1.x, a21); a21 = fmaf(f2.y, w1.y, a21);
        a21 = fmaf(f2.z, w1.z, a21); a21 = fmaf(f2.w, w1.w, a21);
        a30 = fmaf(f3.x, w0.x, a30); a30 = fmaf(f3.y, w0.y, a30);
        a30 = fmaf(f3.z, w0.z, a30); a30 = fmaf(f3.w, w0.w, a30);
        a31 = fmaf(f3.x, w1.x, a31); a31 = fmaf(f3.y, w1.y, a31);
        a31 = fmaf(f3.z, w1.z, a31); a31 = fmaf(f3.w, w1.w, a31);
    }
    out[(row0 + r8     ) * HID + c     ] = a00;
    out[(row0 + r8     ) * HID + c + 32] = a01;
    out[(row0 + r8 +  8) * HID + c     ] = a10;
    out[(row0 + r8 +  8) * HID + c + 32] = a11;
    out[(row0 + r8 + 16) * HID + c     ] = a20;
    out[(row0 + r8 + 16) * HID + c + 32] = a21;
    out[(row0 + r8 + 24) * HID + c     ] = a30;
    out[(row0 + r8 + 24) * HID + c + 32] = a31;
}

// ---------------------------------------------------------------------------
extern "C" void kernel_launch(void* const* d_in, const int* in_sizes, int n_in,
                              void* d_out, int out_size)
{
    const float* feat  = (const float*)d_in[0];
    const int*   src   = (const int*)  d_in[1];
    const int*   dst   = (const int*)  d_in[2];
    const float* W1    = (const float*)d_in[3];
    const float* b1    = (const float*)d_in[4];
    const float* W2    = (const float*)d_in[5];
    const float* b2    = (const float*)d_in[6];
    const float* betas = (const float*)d_in[7];

    __half *h0, *h1; float *rnA, *rnB; int *deg, *off, *cur, *bsum, *csr;
    cudaGetSymbolAddress((void**)&h0,   g_h0);
    cudaGetSymbolAddress((void**)&h1,   g_h1);
    cudaGetSymbolAddress((void**)&rnA,  g_rnA);
    cudaGetSymbolAddress((void**)&rnB,  g_rnB);
    cudaGetSymbolAddress((void**)&deg,  g_deg);
    cudaGetSymbolAddress((void**)&off,  g_off);
    cudaGetSymbolAddress((void**)&cur,  g_cur);
    cudaGetSymbolAddress((void**)&bsum, g_bsum);
    cudaGetSymbolAddress((void**)&csr,  g_csr);

    hist_kernel<<<N_EDGES / 4 / 256, 256>>>(dst, deg, bsum);
    scanF_kernel<<<N_NODES / 256, 256>>>(bsum, deg, off, cur);
    projscatter_kernel<<<N_NODES / 16, 256>>>(src, dst, cur, csr, bsum,
                                              feat, W1, b1, h0, rnA);
    layer_kernel<<<N_NODES * 32 / 256, 256>>>(csr, off, h0, rnA, betas, 0, h1, rnB);
    layer_kernel<<<N_NODES * 32 / 256, 256>>>(csr, off, h1, rnB, betas, 1, h0, rnA);
    cls_kernel<<<N_NODES / 32, 256>>>(h0, W2, b2, (float*)d_out);
}

// round 12
// speedup vs baseline: 2.2478x; 1.0253x over previous
#include <cuda_runtime.h>
#include <cuda_fp16.h>
#include <math_constants.h>

#define N_NODES 65536
#define N_EDGES 1048576
#define IN_F 128
#define HID 64
#define L2E 1.44269504088896f   // log2(e)
#define LN2 0.69314718055995f   // 1/log2(e)

// ---------------- scratch (device globals; no allocation allowed) ----------
__device__ __half g_h0[N_NODES * HID];  // 8 MB, fp16 node features ping
__device__ __half g_h1[N_NODES * HID];  // 8 MB, pong
__device__ float  g_rnA[N_NODES];       // log2e / max(||h||, eps)  (pre-scaled!)
__device__ float  g_rnB[N_NODES];       // pong
__device__ int    g_deg[N_NODES];       // zeroed by scanF each pass
__device__ int    g_off[N_NODES + 1];
__device__ int    g_cur[N_NODES];
__device__ int    g_bsum[256];          // chunk sums; zeroed by projscatter
__device__ int    g_csr[N_EDGES];       // src node id, grouped by dst

// ---------------- launch 1: histogram (node deg + smem-staged chunk sums) --
__global__ __launch_bounds__(256) void hist_kernel(
    const int* __restrict__ dst, int* __restrict__ deg, int* __restrict__ bsum)
{
    __shared__ int sc[256];
    int t = threadIdx.x;
    sc[t] = 0;
    __syncthreads();
    int i = blockIdx.x * 256 + t;
    int4 d = __ldg((const int4*)dst + i);
    atomicAdd(deg + d.x, 1);
    atomicAdd(deg + d.y, 1);
    atomicAdd(deg + d.z, 1);
    atomicAdd(deg + d.w, 1);
    atomicAdd(sc + (d.x >> 8), 1);
    atomicAdd(sc + (d.y >> 8), 1);
    atomicAdd(sc + (d.z >> 8), 1);
    atomicAdd(sc + (d.w >> 8), 1);
    __syncthreads();
    int v = sc[t];
    if (v) atomicAdd(bsum + t, v);      // 256 spread addresses per block
}

// ---------------- launch 2: fused scan (block-local + chunk) + deg reset ---
__global__ __launch_bounds__(256) void scanF_kernel(
    const int* __restrict__ bsum, int* __restrict__ deg,
    int* __restrict__ off, int* __restrict__ cur)
{
    __shared__ int s[256];
    __shared__ int sb[256];
    int t = threadIdx.x;
    int b = blockIdx.x;
    int g = b * 256 + t;
    int d = deg[g];
    deg[g] = 0;                          // reset for next graph replay
    s[t]  = d;
    sb[t] = bsum[t];
    __syncthreads();
#pragma unroll
    for (int o = 1; o < 256; o <<= 1) {
        int v1 = (t >= o) ? s[t - o]  : 0;
        int v2 = (t >= o) ? sb[t - o] : 0;
        __syncthreads();
        s[t] += v1; sb[t] += v2;
        __syncthreads();
    }
    int excl_blk = sb[b] - bsum[b];      // exclusive chunk prefix
    int v = (s[t] - d) + excl_blk;       // global exclusive offset
    off[g] = v;
    cur[g] = v;
    if (g == 0) off[N_NODES] = N_EDGES;
}

// ---------------- launch 3: scatter + proj GEMM (fused, fp16 out) ----------
__global__ __launch_bounds__(256) void projscatter_kernel(
    const int* __restrict__ src, const int* __restrict__ dst,
    int* __restrict__ cur, int* __restrict__ csr, int* __restrict__ bsum,
    const float* __restrict__ feat, const float* __restrict__ W1,
    const float* __restrict__ b1, __half* __restrict__ out,
    float* __restrict__ rn)
{
    __shared__ float sF[16][IN_F];        // 8 KB
    __shared__ float sWt[HID][132];       // 33.8 KB, padded
    int tid = threadIdx.x;

    // --- scatter: 1 edge per thread (grid 4096 * 256 = N_EDGES) ---
    {
        int e = blockIdx.x * 256 + tid;
        int p = atomicAdd(cur + __ldg(dst + e), 1);
        csr[p] = __ldg(src + e);
    }
    if (blockIdx.x == 0) bsum[tid] = 0;   // reset chunk sums for next replay

    // --- proj tiles ---
    int row0 = blockIdx.x * 16;
    for (int i = tid; i < 16 * IN_F; i += 256)
        sF[i >> 7][i & 127] = feat[row0 * IN_F + i];
    for (int i = tid; i < IN_F * HID; i += 256) {
        int k = i >> 6, j = i & 63;
        sWt[j][k] = W1[i];
    }
    __syncthreads();

    int r8 = tid >> 5, c = tid & 31;
    float bc0 = b1[c], bc1 = b1[c + 32];
    float a00 = bc0, a01 = bc1;
    float a10 = bc0, a11 = bc1;
#pragma unroll
    for (int k4 = 0; k4 < IN_F / 4; k4++) {
        float4 w0 = *(const float4*)&sWt[c     ][k4 * 4];
        float4 w1 = *(const float4*)&sWt[c + 32][k4 * 4];
        float4 f0 = *(const float4*)&sF[r8    ][k4 * 4];
        float4 f1 = *(const float4*)&sF[r8 + 8][k4 * 4];
        a00 = fmaf(f0.x, w0.x, a00); a00 = fmaf(f0.y, w0.y, a00);
        a00 = fmaf(f0.z, w0.z, a00); a00 = fmaf(f0.w, w0.w, a00);
        a01 = fmaf(f0.x, w1.x, a01); a01 = fmaf(f0.y, w1.y, a01);
        a01 = fmaf(f0.z, w1.z, a01); a01 = fmaf(f0.w, w1.w, a01);
        a10 = fmaf(f1.x, w0.x, a10); a10 = fmaf(f1.y, w0.y, a10);
        a10 = fmaf(f1.z, w0.z, a10); a10 = fmaf(f1.w, w0.w, a10);
        a11 = fmaf(f1.x, w1.x, a11); a11 = fmaf(f1.y, w1.y, a11);
        a11 = fmaf(f1.z, w1.z, a11); a11 = fmaf(f1.w, w1.w, a11);
    }
    a00 = fmaxf(a00, 0.0f); a01 = fmaxf(a01, 0.0f);
    a10 = fmaxf(a10, 0.0f); a11 = fmaxf(a11, 0.0f);
    out[(row0 + r8    ) * HID + c     ] = __float2half_rn(a00);
    out[(row0 + r8    ) * HID + c + 32] = __float2half_rn(a01);
    out[(row0 + r8 + 8) * HID + c     ] = __float2half_rn(a10);
    out[(row0 + r8 + 8) * HID + c + 32] = __float2half_rn(a11);
    float p0 = a00 * a00 + a01 * a01;
    float p1 = a10 * a10 + a11 * a11;
#pragma unroll
    for (int o = 16; o; o >>= 1) {
        p0 += __shfl_xor_sync(0xffffffffu, p0, o);
        p1 += __shfl_xor_sync(0xffffffffu, p1, o);
    }
    if (c == 0) {
        rn[row0 + r8    ] = L2E / fmaxf(sqrtf(p0), 1e-12f);
        rn[row0 + r8 + 8] = L2E / fmaxf(sqrtf(p1), 1e-12f);
    }
}

// ---------------- fp16 pack/unpack helpers ---------------------------------
__device__ __forceinline__ void unpack8(uint4 r, float* f) {
    float2 t;
    t = __half22float2(*reinterpret_cast<__half2*>(&r.x)); f[0] = t.x; f[1] = t.y;
    t = __half22float2(*reinterpret_cast<__half2*>(&r.y)); f[2] = t.x; f[3] = t.y;
    t = __half22float2(*reinterpret_cast<__half2*>(&r.z)); f[4] = t.x; f[5] = t.y;
    t = __half22float2(*reinterpret_cast<__half2*>(&r.w)); f[6] = t.x; f[7] = t.y;
}
__device__ __forceinline__ uint4 pack8(const float* f) {
    uint4 r;
    __half2 p;
    p = __floats2half2_rn(f[0], f[1]); r.x = *reinterpret_cast<unsigned*>(&p);
    p = __floats2half2_rn(f[2], f[3]); r.y = *reinterpret_cast<unsigned*>(&p);
    p = __floats2half2_rn(f[4], f[5]); r.z = *reinterpret_cast<unsigned*>(&p);
    p = __floats2half2_rn(f[6], f[7]); r.w = *reinterpret_cast<unsigned*>(&p);
    return r;
}
__device__ __forceinline__ float ex2f(float x) {
    float y;
    asm("ex2.approx.ftz.f32 %0, %1;" : "=f"(y) : "f"(x));
    return y;
}

// ---------------- launches 4,5: fused AGNN layer ---------------------------
// Flat edge loop, direct per-quarter loads (no warp staging / broadcasts),
// 3 named pipeline slots (no register-rotation MOVs).
// qtr = lane>>3 owns edges e = s0+qtr, +4, +8...; sub = lane&7 owns feature
// elems [sub*8, sub*8+8) as ONE uint4 (128B line per node row).
// rn_in is pre-scaled by log2e; weights via single EX2.
#define PREF(E, SN, RS, RAW)                                              \
    {                                                                     \
        int cidx = min(E, s1 - 1);                                        \
        SN = __ldg(csr + cidx);                                           \
        RS = __ldg(rn_in + SN);                                           \
        RAW = *(const uint4*)(hh + SN * HID + sub * 8);                   \
    }
#define BODY(E, SN, RS, RAW)                                              \
    {                                                                     \
        float f[8];                                                       \
        unpack8(RAW, f);                                                  \
        float dt = q[0]*f[0] + q[1]*f[1] + q[2]*f[2] + q[3]*f[3]          \
                 + q[4]*f[4] + q[5]*f[5] + q[6]*f[6] + q[7]*f[7];         \
        dt += __shfl_xor_sync(FULL, dt, 1);                               \
        dt += __shfl_xor_sync(FULL, dt, 2);                               \
        dt += __shfl_xor_sync(FULL, dt, 4);                               \
        float w = ex2f(fmaf(dt, RS, mB2));                                \
        w = (E < s1) ? w : 0.0f;                                          \
        ss += w;                                                          \
        acc[0] = fmaf(w, f[0], acc[0]); acc[1] = fmaf(w, f[1], acc[1]);   \
        acc[2] = fmaf(w, f[2], acc[2]); acc[3] = fmaf(w, f[3], acc[3]);   \
        acc[4] = fmaf(w, f[4], acc[4]); acc[5] = fmaf(w, f[5], acc[5]);   \
        acc[6] = fmaf(w, f[6], acc[6]); acc[7] = fmaf(w, f[7], acc[7]);   \
        E += 12;                                                          \
        PREF(E, SN, RS, RAW)                                              \
    }

__global__ __launch_bounds__(256) void layer_kernel(
    const int* __restrict__ csr, const int* __restrict__ off,
    const __half* __restrict__ hh, const float* __restrict__ rn_in,
    const float* __restrict__ betas, int layer,
    __half* __restrict__ out_h, float* __restrict__ rn_out)
{
    int node = (blockIdx.x * blockDim.x + threadIdx.x) >> 5;
    int lane = threadIdx.x & 31;
    int qtr  = lane >> 3;
    int sub  = lane & 7;
    const unsigned FULL = 0xffffffffu;

    int s0 = off[node], s1 = off[node + 1];
    int deg = s1 - s0;
    float beta = __ldg(betas + layer);
    float mB2 = -fabsf(beta) * L2E;               // -log2e * max logit
    float q[8];
    {
        uint4 qraw = *(const uint4*)(hh + node * HID + sub * 8);
        unpack8(qraw, q);
        float qs = beta * rn_in[node] * LN2;      // undo the log2e pre-scale
#pragma unroll
        for (int i = 0; i < 8; i++) q[i] *= qs;
    }

    float ss = 0.0f;
    float acc[8] = {0.f, 0.f, 0.f, 0.f, 0.f, 0.f, 0.f, 0.f};

    if (deg > 0) {
        int eA = s0 + qtr, eB = eA + 4, eC = eA + 8;
        int snA, snB, snC; float rsA, rsB, rsC; uint4 rawA, rawB, rawC;
        PREF(eA, snA, rsA, rawA)
        PREF(eB, snB, rsB, rawB)
        PREF(eC, snC, rsC, rawC)
        int nIter = (deg + 11) / 12;
        for (int it = 0; it < nIter; it++) {
            BODY(eA, snA, rsA, rawA)
            BODY(eB, snB, rsB, rawB)
            BODY(eC, snC, rsC, rawC)
        }
    }
    // combine the 4 quarters
#pragma unroll
    for (int i = 0; i < 8; i++) {
        acc[i] += __shfl_xor_sync(FULL, acc[i], 8);
        acc[i] += __shfl_xor_sync(FULL, acc[i], 16);
    }
    ss += __shfl_xor_sync(FULL, ss, 8);
    ss += __shfl_xor_sync(FULL, ss, 16);
    float inv = (deg > 0) ? __frcp_rn(ss) : 0.0f;
    float ns = 0.0f;
#pragma unroll
    for (int i = 0; i < 8; i++) {
        acc[i] *= inv;
        ns = fmaf(acc[i], acc[i], ns);
    }
    ns += __shfl_xor_sync(FULL, ns, 1);
    ns += __shfl_xor_sync(FULL, ns, 2);
    ns += __shfl_xor_sync(FULL, ns, 4);
    if (qtr == 0) {
        *(uint4*)(out_h + node * HID + sub * 8) = pack8(acc);
        if (sub == 0)
            rn_out[node] = L2E / fmaxf(sqrtf(ns), 1e-12f);
    }
}

// ---------------- launch 6: cls = h(fp16) @ W2 + b2, 32 rows/block ---------
__global__ __launch_bounds__(256) void cls_kernel(
    const __half* __restrict__ hh, const float* __restrict__ W2,
    const float* __restrict__ b2, float* __restrict__ out)
{
    __shared__ float sF[32][HID];         // 8 KB
    __shared__ float sWt[HID][68];        // 17.4 KB, padded
    int tid = threadIdx.x;
    int row0 = blockIdx.x * 32;
    for (int i = tid; i < 32 * HID; i += 256)
        sF[i >> 6][i & 63] = __half2float(hh[row0 * HID + i]);
    for (int i = tid; i < HID * HID; i += 256) {
        int k = i >> 6, j = i & 63;
        sWt[j][k] = W2[i];
    }
    __syncthreads();

    int r8 = tid >> 5, c = tid & 31;
    float bc0 = b2[c], bc1 = b2[c + 32];
    float a00 = bc0, a01 = bc1, a10 = bc0, a11 = bc1;
    float a20 = bc0, a21 = bc1, a30 = bc0, a31 = bc1;
#pragma unroll
    for (int k4 = 0; k4 < HID / 4; k4++) {
        float4 w0 = *(const float4*)&sWt[c     ][k4 * 4];
        float4 w1 = *(const float4*)&sWt[c + 32][k4 * 4];
        float4 f0 = *(const float4*)&sF[r8     ][k4 * 4];
        float4 f1 = *(const float4*)&sF[r8 +  8][k4 * 4];
        float4 f2 = *(const float4*)&sF[r8 + 16][k4 * 4];
        float4 f3 = *(const float4*)&sF[r8 + 24][k4 * 4];
        a00 = fmaf(f0.x, w0.x, a00); a00 = fmaf(f0.y, w0.y, a00);
        a00 = fmaf(f0.z, w0.z, a00); a00 = fmaf(f0.w, w0.w, a00);
        a01 = fmaf(f0.x, w1.x, a01); a01 = fmaf(f0.y, w1.y, a01);
        a01 = fmaf(f0.z, w1.z, a01); a01 = fmaf(f0.w, w1.w, a01);
        a10 = fmaf(f1.x, w0.x, a10); a10 = fmaf(f1.y, w0.y, a10);
        a10 = fmaf(f1.z, w0.z, a10); a10 = fmaf(f1.w, w0.w, a10);
        a11 = fmaf(f1.x, w1.x, a11); a11 = fmaf(f1.y, w1.y, a11);
        a11 = fmaf(f1.z, w1.z, a11); a11 = fmaf(f1.w, w1.w, a11);
        a20 = fmaf(f2.x, w0.x, a20); a20 = fmaf(f2.y, w0.y, a20);
        a20 = fmaf(f2.z, w0.z, a20); a20 = fmaf(f2.w, w0.w, a20);
        a21 = fmaf(f2.x, w1.x, a21); a21 = fmaf(f2.y, w1.y, a21);
        a21 = fmaf(f2.z, w1.z, a21); a21 = fmaf(f2.w, w1.w, a21);
        a30 = fmaf(f3.x, w0.x, a30); a30 = fmaf(f3.y, w0.y, a30);
        a30 = fmaf(f3.z, w0.z, a30); a30 = fmaf(f3.w, w0.w, a30);
        a31 = fmaf(f3.x, w1.x, a31); a31 = fmaf(f3.y, w1.y, a31);
        a31 = fmaf(f3.z, w1.z, a31); a31 = fmaf(f3.w, w1.w, a31);
    }
    out[(row0 + r8     ) * HID + c     ] = a00;
    out[(row0 + r8     ) * HID + c + 32] = a01;
    out[(row0 + r8 +  8) * HID + c     ] = a10;
    out[(row0 + r8 +  8) * HID + c + 32] = a11;
    out[(row0 + r8 + 16) * HID + c     ] = a20;
    out[(row0 + r8 + 16) * HID + c + 32] = a21;
    out[(row0 + r8 + 24) * HID + c     ] = a30;
    out[(row0 + r8 + 24) * HID + c + 32] = a31;
}

// ---------------------------------------------------------------------------
extern "C" void kernel_launch(void* const* d_in, const int* in_sizes, int n_in,
                              void* d_out, int out_size)
{
    const float* feat  = (const float*)d_in[0];
    const int*   src   = (const int*)  d_in[1];
    const int*   dst   = (const int*)  d_in[2];
    const float* W1    = (const float*)d_in[3];
    const float* b1    = (const float*)d_in[4];
    const float* W2    = (const float*)d_in[5];
    const float* b2    = (const float*)d_in[6];
    const float* betas = (const float*)d_in[7];

    __half *h0, *h1; float *rnA, *rnB; int *deg, *off, *cur, *bsum, *csr;
    cudaGetSymbolAddress((void**)&h0,   g_h0);
    cudaGetSymbolAddress((void**)&h1,   g_h1);
    cudaGetSymbolAddress((void**)&rnA,  g_rnA);
    cudaGetSymbolAddress((void**)&rnB,  g_rnB);
    cudaGetSymbolAddress((void**)&deg,  g_deg);
    cudaGetSymbolAddress((void**)&off,  g_off);
    cudaGetSymbolAddress((void**)&cur,  g_cur);
    cudaGetSymbolAddress((void**)&bsum, g_bsum);
    cudaGetSymbolAddress((void**)&csr,  g_csr);

    hist_kernel<<<N_EDGES / 4 / 256, 256>>>(dst, deg, bsum);
    scanF_kernel<<<N_NODES / 256, 256>>>(bsum, deg, off, cur);
    projscatter_kernel<<<N_NODES / 16, 256>>>(src, dst, cur, csr, bsum,
                                              feat, W1, b1, h0, rnA);
    layer_kernel<<<N_NODES * 32 / 256, 256>>>(csr, off, h0, rnA, betas, 0, h1, rnB);
    layer_kernel<<<N_NODES * 32 / 256, 256>>>(csr, off, h1, rnB, betas, 1, h0, rnA);
    cls_kernel<<<N_NODES / 32, 256>>>(h0, W2, b2, (float*)d_out);
}

// round 13
// speedup vs baseline: 2.2751x; 1.0122x over previous
#include <cuda_runtime.h>
#include <cuda_fp16.h>
#include <math_constants.h>

#define N_NODES 65536
#define N_EDGES 1048576
#define IN_F 128
#define HID 64
#define L2E 1.44269504088896f   // log2(e)
#define LN2 0.69314718055995f   // 1/log2(e)

// ---------------- scratch (device globals; no allocation allowed) ----------
__device__ __half g_h0[N_NODES * HID];  // 8 MB, fp16 node features ping
__device__ __half g_h1[N_NODES * HID];  // 8 MB, pong
__device__ float  g_rnA[N_NODES];       // log2e / max(||h||, eps)  (pre-scaled!)
__device__ float  g_rnB[N_NODES];       // pong
__device__ int    g_deg[N_NODES];       // zeroed by scanF each pass
__device__ int    g_off[N_NODES + 1];
__device__ int    g_cur[N_NODES];
__device__ int    g_bsum[256];          // chunk sums; zeroed by projscatter
__device__ int    g_csr[N_EDGES];       // src node id, grouped by dst

// ---------------- launch 1: histogram (node deg + smem-staged chunk sums) --
__global__ __launch_bounds__(256) void hist_kernel(
    const int* __restrict__ dst, int* __restrict__ deg, int* __restrict__ bsum)
{
    __shared__ int sc[256];
    int t = threadIdx.x;
    sc[t] = 0;
    __syncthreads();
    int i = blockIdx.x * 256 + t;
    int4 d = __ldg((const int4*)dst + i);
    atomicAdd(deg + d.x, 1);
    atomicAdd(deg + d.y, 1);
    atomicAdd(deg + d.z, 1);
    atomicAdd(deg + d.w, 1);
    atomicAdd(sc + (d.x >> 8), 1);
    atomicAdd(sc + (d.y >> 8), 1);
    atomicAdd(sc + (d.z >> 8), 1);
    atomicAdd(sc + (d.w >> 8), 1);
    __syncthreads();
    int v = sc[t];
    if (v) atomicAdd(bsum + t, v);      // 256 spread addresses per block
}

// ---------------- launch 2: fused scan (block-local + chunk) + deg reset ---
__global__ __launch_bounds__(256) void scanF_kernel(
    const int* __restrict__ bsum, int* __restrict__ deg,
    int* __restrict__ off, int* __restrict__ cur)
{
    __shared__ int s[256];
    __shared__ int sb[256];
    int t = threadIdx.x;
    int b = blockIdx.x;
    int g = b * 256 + t;
    int d = deg[g];
    deg[g] = 0;                          // reset for next graph replay
    s[t]  = d;
    sb[t] = bsum[t];
    __syncthreads();
#pragma unroll
    for (int o = 1; o < 256; o <<= 1) {
        int v1 = (t >= o) ? s[t - o]  : 0;
        int v2 = (t >= o) ? sb[t - o] : 0;
        __syncthreads();
        s[t] += v1; sb[t] += v2;
        __syncthreads();
    }
    int excl_blk = sb[b] - bsum[b];      // exclusive chunk prefix
    int v = (s[t] - d) + excl_blk;       // global exclusive offset
    off[g] = v;
    cur[g] = v;
    if (g == 0) off[N_NODES] = N_EDGES;
}

// ---------------- launch 3: scatter + proj GEMM (fused, fp16 out) ----------
__global__ __launch_bounds__(256) void projscatter_kernel(
    const int* __restrict__ src, const int* __restrict__ dst,
    int* __restrict__ cur, int* __restrict__ csr, int* __restrict__ bsum,
    const float* __restrict__ feat, const float* __restrict__ W1,
    const float* __restrict__ b1, __half* __restrict__ out,
    float* __restrict__ rn)
{
    __shared__ float sF[16][IN_F];        // 8 KB
    __shared__ float sWt[HID][132];       // 33.8 KB, padded
    int tid = threadIdx.x;

    // --- scatter: 1 edge per thread (grid 4096 * 256 = N_EDGES) ---
    {
        int e = blockIdx.x * 256 + tid;
        int p = atomicAdd(cur + __ldg(dst + e), 1);
        csr[p] = __ldg(src + e);
    }
    if (blockIdx.x == 0) bsum[tid] = 0;   // reset chunk sums for next replay

    // --- proj tiles ---
    int row0 = blockIdx.x * 16;
    for (int i = tid; i < 16 * IN_F; i += 256)
        sF[i >> 7][i & 127] = feat[row0 * IN_F + i];
    for (int i = tid; i < IN_F * HID; i += 256) {
        int k = i >> 6, j = i & 63;
        sWt[j][k] = W1[i];
    }
    __syncthreads();

    int r8 = tid >> 5, c = tid & 31;
    float bc0 = b1[c], bc1 = b1[c + 32];
    float a00 = bc0, a01 = bc1;
    float a10 = bc0, a11 = bc1;
#pragma unroll
    for (int k4 = 0; k4 < IN_F / 4; k4++) {
        float4 w0 = *(const float4*)&sWt[c     ][k4 * 4];
        float4 w1 = *(const float4*)&sWt[c + 32][k4 * 4];
        float4 f0 = *(const float4*)&sF[r8    ][k4 * 4];
        float4 f1 = *(const float4*)&sF[r8 + 8][k4 * 4];
        a00 = fmaf(f0.x, w0.x, a00); a00 = fmaf(f0.y, w0.y, a00);
        a00 = fmaf(f0.z, w0.z, a00); a00 = fmaf(f0.w, w0.w, a00);
        a01 = fmaf(f0.x, w1.x, a01); a01 = fmaf(f0.y, w1.y, a01);
        a01 = fmaf(f0.z, w1.z, a01); a01 = fmaf(f0.w, w1.w, a01);
        a10 = fmaf(f1.x, w0.x, a10); a10 = fmaf(f1.y, w0.y, a10);
        a10 = fmaf(f1.z, w0.z, a10); a10 = fmaf(f1.w, w0.w, a10);
        a11 = fmaf(f1.x, w1.x, a11); a11 = fmaf(f1.y, w1.y, a11);
        a11 = fmaf(f1.z, w1.z, a11); a11 = fmaf(f1.w, w1.w, a11);
    }
    a00 = fmaxf(a00, 0.0f); a01 = fmaxf(a01, 0.0f);
    a10 = fmaxf(a10, 0.0f); a11 = fmaxf(a11, 0.0f);
    out[(row0 + r8    ) * HID + c     ] = __float2half_rn(a00);
    out[(row0 + r8    ) * HID + c + 32] = __float2half_rn(a01);
    out[(row0 + r8 + 8) * HID + c     ] = __float2half_rn(a10);
    out[(row0 + r8 + 8) * HID + c + 32] = __float2half_rn(a11);
    float p0 = a00 * a00 + a01 * a01;
    float p1 = a10 * a10 + a11 * a11;
#pragma unroll
    for (int o = 16; o; o >>= 1) {
        p0 += __shfl_xor_sync(0xffffffffu, p0, o);
        p1 += __shfl_xor_sync(0xffffffffu, p1, o);
    }
    if (c == 0) {
        rn[row0 + r8    ] = L2E / fmaxf(sqrtf(p0), 1e-12f);
        rn[row0 + r8 + 8] = L2E / fmaxf(sqrtf(p1), 1e-12f);
    }
}

// ---------------- fp16 pack/unpack helpers ---------------------------------
__device__ __forceinline__ void unpack8(uint4 r, float* f) {
    float2 t;
    t = __half22float2(*reinterpret_cast<__half2*>(&r.x)); f[0] = t.x; f[1] = t.y;
    t = __half22float2(*reinterpret_cast<__half2*>(&r.y)); f[2] = t.x; f[3] = t.y;
    t = __half22float2(*reinterpret_cast<__half2*>(&r.z)); f[4] = t.x; f[5] = t.y;
    t = __half22float2(*reinterpret_cast<__half2*>(&r.w)); f[6] = t.x; f[7] = t.y;
}
__device__ __forceinline__ uint4 pack8(const float* f) {
    uint4 r;
    __half2 p;
    p = __floats2half2_rn(f[0], f[1]); r.x = *reinterpret_cast<unsigned*>(&p);
    p = __floats2half2_rn(f[2], f[3]); r.y = *reinterpret_cast<unsigned*>(&p);
    p = __floats2half2_rn(f[4], f[5]); r.z = *reinterpret_cast<unsigned*>(&p);
    p = __floats2half2_rn(f[6], f[7]); r.w = *reinterpret_cast<unsigned*>(&p);
    return r;
}
__device__ __forceinline__ float ex2f(float x) {
    float y;
    asm("ex2.approx.ftz.f32 %0, %1;" : "=f"(y) : "f"(x));
    return y;
}

// ---------------- launches 4,5: fused AGNN layer ---------------------------
// Flat edge loop, per-quarter direct loads, 3 named pipeline slots executed
// in cyclic order at 4-edge granularity: nIter = ceil(deg/4) BODYs total
// (was: blocks of 3 BODYs = 12-slot quantization, ~4.5x issue waste).
#define PREF(E, SN, RS, RAW)                                              \
    {                                                                     \
        int cidx = min(E, s1m1);                                          \
        SN = __ldg(csr + cidx);                                           \
        RS = __ldg(rn_in + SN);                                           \
        RAW = *(const uint4*)(hh + SN * HID + sub * 8);                   \
    }
#define BODY(E, SN, RS, RAW)                                              \
    {                                                                     \
        float f[8];                                                       \
        unpack8(RAW, f);                                                  \
        float dt = q[0]*f[0] + q[1]*f[1] + q[2]*f[2] + q[3]*f[3]          \
                 + q[4]*f[4] + q[5]*f[5] + q[6]*f[6] + q[7]*f[7];         \
        dt += __shfl_xor_sync(FULL, dt, 1);                               \
        dt += __shfl_xor_sync(FULL, dt, 2);                               \
        dt += __shfl_xor_sync(FULL, dt, 4);                               \
        float w = ex2f(fmaf(dt, RS, mB2));                                \
        w = (E < s1) ? w : 0.0f;                                          \
        ss += w;                                                          \
        acc[0] = fmaf(w, f[0], acc[0]); acc[1] = fmaf(w, f[1], acc[1]);   \
        acc[2] = fmaf(w, f[2], acc[2]); acc[3] = fmaf(w, f[3], acc[3]);   \
        acc[4] = fmaf(w, f[4], acc[4]); acc[5] = fmaf(w, f[5], acc[5]);   \
        acc[6] = fmaf(w, f[6], acc[6]); acc[7] = fmaf(w, f[7], acc[7]);   \
        E += 12;                                                          \
        PREF(E, SN, RS, RAW)                                              \
    }

__global__ __launch_bounds__(256) void layer_kernel(
    const int* __restrict__ csr, const int* __restrict__ off,
    const __half* __restrict__ hh, const float* __restrict__ rn_in,
    const float* __restrict__ betas, int layer,
    __half* __restrict__ out_h, float* __restrict__ rn_out)
{
    int node = (blockIdx.x * blockDim.x + threadIdx.x) >> 5;
    int lane = threadIdx.x & 31;
    int qtr  = lane >> 3;
    int sub  = lane & 7;
    const unsigned FULL = 0xffffffffu;

    int s0 = off[node], s1 = off[node + 1];
    int deg = s1 - s0;
    int s1m1 = s1 - 1;
    float beta = __ldg(betas + layer);
    float mB2 = -fabsf(beta) * L2E;               // -log2e * max logit
    float q[8];
    {
        uint4 qraw = *(const uint4*)(hh + node * HID + sub * 8);
        unpack8(qraw, q);
        float qs = beta * rn_in[node] * LN2;      // undo the log2e pre-scale
#pragma unroll
        for (int i = 0; i < 8; i++) q[i] *= qs;
    }

    float ss = 0.0f;
    float acc[8] = {0.f, 0.f, 0.f, 0.f, 0.f, 0.f, 0.f, 0.f};

    if (deg > 0) {
        int eA = s0 + qtr, eB = eA + 4, eC = eA + 8;
        int snA, snB, snC; float rsA, rsB, rsC; uint4 rawA, rawB, rawC;
        PREF(eA, snA, rsA, rawA)
        PREF(eB, snB, rsB, rawB)
        PREF(eC, snC, rsC, rawC)
        int nIter = (deg + 3) >> 2;               // 4-edge chunks
        while (nIter >= 3) {
            BODY(eA, snA, rsA, rawA)
            BODY(eB, snB, rsB, rawB)
            BODY(eC, snC, rsC, rawC)
            nIter -= 3;
        }
        if (nIter >= 1) { BODY(eA, snA, rsA, rawA) }
        if (nIter == 2) { BODY(eB, snB, rsB, rawB) }
    }
    // combine the 4 quarters
#pragma unroll
    for (int i = 0; i < 8; i++) {
        acc[i] += __shfl_xor_sync(FULL, acc[i], 8);
        acc[i] += __shfl_xor_sync(FULL, acc[i], 16);
    }
    ss += __shfl_xor_sync(FULL, ss, 8);
    ss += __shfl_xor_sync(FULL, ss, 16);
    float inv = (deg > 0) ? __frcp_rn(ss) : 0.0f;
    float ns = 0.0f;
#pragma unroll
    for (int i = 0; i < 8; i++) {
        acc[i] *= inv;
        ns = fmaf(acc[i], acc[i], ns);
    }
    ns += __shfl_xor_sync(FULL, ns, 1);
    ns += __shfl_xor_sync(FULL, ns, 2);
    ns += __shfl_xor_sync(FULL, ns, 4);
    if (qtr == 0) {
        *(uint4*)(out_h + node * HID + sub * 8) = pack8(acc);
        if (sub == 0)
            rn_out[node] = L2E / fmaxf(sqrtf(ns), 1e-12f);
    }
}

// ---------------- launch 6: cls = h(fp16) @ W2 + b2, 32 rows/block ---------
__global__ __launch_bounds__(256) void cls_kernel(
    const __half* __restrict__ hh, const float* __restrict__ W2,
    const float* __restrict__ b2, float* __restrict__ out)
{
    __shared__ float sF[32][HID];         // 8 KB
    __shared__ float sWt[HID][68];        // 17.4 KB, padded
    int tid = threadIdx.x;
    int row0 = blockIdx.x * 32;
    for (int i = tid; i < 32 * HID; i += 256)
        sF[i >> 6][i & 63] = __half2float(hh[row0 * HID + i]);
    for (int i = tid; i < HID * HID; i += 256) {
        int k = i >> 6, j = i & 63;
        sWt[j][k] = W2[i];
    }
    __syncthreads();

    int r8 = tid >> 5, c = tid & 31;
    float bc0 = b2[c], bc1 = b2[c + 32];
    float a00 = bc0, a01 = bc1, a10 = bc0, a11 = bc1;
    float a20 = bc0, a21 = bc1, a30 = bc0, a31 = bc1;
#pragma unroll
    for (int k4 = 0; k4 < HID / 4; k4++) {
        float4 w0 = *(const float4*)&sWt[c     ][k4 * 4];
        float4 w1 = *(const float4*)&sWt[c + 32][k4 * 4];
        float4 f0 = *(const float4*)&sF[r8     ][k4 * 4];
        float4 f1 = *(const float4*)&sF[r8 +  8][k4 * 4];
        float4 f2 = *(const float4*)&sF[r8 + 16][k4 * 4];
        float4 f3 = *(const float4*)&sF[r8 + 24][k4 * 4];
        a00 = fmaf(f0.x, w0.x, a00); a00 = fmaf(f0.y, w0.y, a00);
        a00 = fmaf(f0.z, w0.z, a00); a00 = fmaf(f0.w, w0.w, a00);
        a01 = fmaf(f0.x, w1.x, a01); a01 = fmaf(f0.y, w1.y, a01);
        a01 = fmaf(f0.z, w1.z, a01); a01 = fmaf(f0.w, w1.w, a01);
        a10 = fmaf(f1.x, w0.x, a10); a10 = fmaf(f1.y, w0.y, a10);
        a10 = fmaf(f1.z, w0.z, a10); a10 = fmaf(f1.w, w0.w, a10);
        a11 = fmaf(f1.x, w1.x, a11); a11 = fmaf(f1.y, w1.y, a11);
        a11 = fmaf(f1.z, w1.z, a11); a11 = fmaf(f1.w, w1.w, a11);
        a20 = fmaf(f2.x, w0.x, a20); a20 = fmaf(f2.y, w0.y, a20);
        a20 = fmaf(f2.z, w0.z, a20); a20 = fmaf(f2.w, w0.w, a20);
        a21 = fmaf(f2.x, w1.x, a21); a21 = fmaf(f2.y, w1.y, a21);
        a21 = fmaf(f2.z, w1.z, a21); a21 = fmaf(f2.w, w1.w, a21);
        a30 = fmaf(f3.x, w0.x, a30); a30 = fmaf(f3.y, w0.y, a30);
        a30 = fmaf(f3.z, w0.z, a30); a30 = fmaf(f3.w, w0.w, a30);
        a31 = fmaf(f3.x, w1.x, a31); a31 = fmaf(f3.y, w1.y, a31);
        a31 = fmaf(f3.z, w1.z, a31); a31 = fmaf(f3.w, w1.w, a31);
    }
    out[(row0 + r8     ) * HID + c     ] = a00;
    out[(row0 + r8     ) * HID + c + 32] = a01;
    out[(row0 + r8 +  8) * HID + c     ] = a10;
    out[(row0 + r8 +  8) * HID + c + 32] = a11;
    out[(row0 + r8 + 16) * HID + c     ] = a20;
    out[(row0 + r8 + 16) * HID + c + 32] = a21;
    out[(row0 + r8 + 24) * HID + c     ] = a30;
    out[(row0 + r8 + 24) * HID + c + 32] = a31;
}

// ---------------------------------------------------------------------------
extern "C" void kernel_launch(void* const* d_in, const int* in_sizes, int n_in,
                              void* d_out, int out_size)
{
    const float* feat  = (const float*)d_in[0];
    const int*   src   = (const int*)  d_in[1];
    const int*   dst   = (const int*)  d_in[2];
    const float* W1    = (const float*)d_in[3];
    const float* b1    = (const float*)d_in[4];
    const float* W2    = (const float*)d_in[5];
    const float* b2    = (const float*)d_in[6];
    const float* betas = (const float*)d_in[7];

    __half *h0, *h1; float *rnA, *rnB; int *deg, *off, *cur, *bsum, *csr;
    cudaGetSymbolAddress((void**)&h0,   g_h0);
    cudaGetSymbolAddress((void**)&h1,   g_h1);
    cudaGetSymbolAddress((void**)&rnA,  g_rnA);
    cudaGetSymbolAddress((void**)&rnB,  g_rnB);
    cudaGetSymbolAddress((void**)&deg,  g_deg);
    cudaGetSymbolAddress((void**)&off,  g_off);
    cudaGetSymbolAddress((void**)&cur,  g_cur);
    cudaGetSymbolAddress((void**)&bsum, g_bsum);
    cudaGetSymbolAddress((void**)&csr,  g_csr);

    hist_kernel<<<N_EDGES / 4 / 256, 256>>>(dst, deg, bsum);
    scanF_kernel<<<N_NODES / 256, 256>>>(bsum, deg, off, cur);
    projscatter_kernel<<<N_NODES / 16, 256>>>(src, dst, cur, csr, bsum,
                                              feat, W1, b1, h0, rnA);
    layer_kernel<<<N_NODES * 32 / 256, 256>>>(csr, off, h0, rnA, betas, 0, h1, rnB);
    layer_kernel<<<N_NODES * 32 / 256, 256>>>(csr, off, h1, rnB, betas, 1, h0, rnA);
    cls_kernel<<<N_NODES / 32, 256>>>(h0, W2, b2, (float*)d_out);
}

// round 15
// speedup vs baseline: 2.3997x; 1.0548x over previous
#include <cuda_runtime.h>
#include <cuda_fp16.h>
#include <math_constants.h>

#define N_NODES 65536
#define N_EDGES 1048576
#define IN_F 128
#define HID 64
#define L2E 1.44269504088896f   // log2(e)
#define LN2 0.69314718055995f   // 1/log2(e)

// ---------------- scratch (device globals; no allocation allowed) ----------
__device__ __half g_h0[N_NODES * HID];  // 8 MB, fp16 node features ping
__device__ __half g_h1[N_NODES * HID];  // 8 MB, pong
__device__ float  g_rnA[N_NODES];       // log2e / max(||h||, eps)  (pre-scaled!)
__device__ float  g_rnB[N_NODES];       // pong
__device__ int    g_deg[N_NODES];       // zeroed by scanF each pass
__device__ int    g_off[N_NODES + 1];
__device__ int    g_cur[N_NODES];
__device__ int    g_bsum[256];          // chunk sums; zeroed by projscatter
__device__ int    g_csr[N_EDGES];       // src node id, grouped by dst

// ---------------- packed f32x2 helpers (sm_103a; inline PTX only) ----------
#define MUL2(d, a, b) \
    asm("mul.rn.f32x2 %0, %1, %2;" : "=l"(d) : "l"(a), "l"(b))
#define FMA2(d, a, b, c) \
    asm("fma.rn.f32x2 %0, %1, %2, %3;" : "=l"(d) : "l"(a), "l"(b), "l"(c))

__device__ __forceinline__ unsigned long long h2f2(unsigned h2v) {
    float2 t = __half22float2(*reinterpret_cast<const __half2*>(&h2v));
    unsigned long long p;
    asm("mov.b64 %0, {%1, %2};"
        : "=l"(p) : "r"(__float_as_uint(t.x)), "r"(__float_as_uint(t.y)));
    return p;
}
__device__ __forceinline__ void unpk2(unsigned long long p, float& lo, float& hi) {
    unsigned a, b;
    asm("mov.b64 {%0, %1}, %2;" : "=r"(a), "=r"(b) : "l"(p));
    lo = __uint_as_float(a); hi = __uint_as_float(b);
}
__device__ __forceinline__ float ex2f(float x) {
    float y;
    asm("ex2.approx.ftz.f32 %0, %1;" : "=f"(y) : "f"(x));
    return y;
}

// ---------------- launch 1: histogram, 8 edges/thread ----------------------
__global__ __launch_bounds__(256) void hist_kernel(
    const int* __restrict__ dst, int* __restrict__ deg, int* __restrict__ bsum)
{
    __shared__ int sc[256];
    int t = threadIdx.x;
    sc[t] = 0;
    __syncthreads();
    int i = blockIdx.x * 256 + t;
    int4 d0 = __ldg((const int4*)dst + 2 * i);
    int4 d1 = __ldg((const int4*)dst + 2 * i + 1);
    atomicAdd(deg + d0.x, 1); atomicAdd(deg + d0.y, 1);
    atomicAdd(deg + d0.z, 1); atomicAdd(deg + d0.w, 1);
    atomicAdd(deg + d1.x, 1); atomicAdd(deg + d1.y, 1);
    atomicAdd(deg + d1.z, 1); atomicAdd(deg + d1.w, 1);
    atomicAdd(sc + (d0.x >> 8), 1); atomicAdd(sc + (d0.y >> 8), 1);
    atomicAdd(sc + (d0.z >> 8), 1); atomicAdd(sc + (d0.w >> 8), 1);
    atomicAdd(sc + (d1.x >> 8), 1); atomicAdd(sc + (d1.y >> 8), 1);
    atomicAdd(sc + (d1.z >> 8), 1); atomicAdd(sc + (d1.w >> 8), 1);
    __syncthreads();
    int v = sc[t];
    if (v) atomicAdd(bsum + t, v);      // 256 spread addresses per block
}

// ---------------- launch 2: fused scan (block-local + chunk) + deg reset ---
__global__ __launch_bounds__(256) void scanF_kernel(
    const int* __restrict__ bsum, int* __restrict__ deg,
    int* __restrict__ off, int* __restrict__ cur)
{
    __shared__ int s[256];
    __shared__ int sb[256];
    int t = threadIdx.x;
    int b = blockIdx.x;
    int g = b * 256 + t;
    int d = deg[g];
    deg[g] = 0;                          // reset for next graph replay
    s[t]  = d;
    sb[t] = bsum[t];
    __syncthreads();
#pragma unroll
    for (int o = 1; o < 256; o <<= 1) {
        int v1 = (t >= o) ? s[t - o]  : 0;
        int v2 = (t >= o) ? sb[t - o] : 0;
        __syncthreads();
        s[t] += v1; sb[t] += v2;
        __syncthreads();
    }
    int excl_blk = sb[b] - bsum[b];      // exclusive chunk prefix
    int v = (s[t] - d) + excl_blk;       // global exclusive offset
    off[g] = v;
    cur[g] = v;
    if (g == 0) off[N_NODES] = N_EDGES;
}

// ---------------- launch 3: scatter (2 e/thread) + proj GEMM (32 rows) -----
// No sF staging: feat is read as warp-broadcast float4 loads (all 32 lanes of
// a warp share the same row r8 -> single L1 wavefront per load).
__global__ __launch_bounds__(256) void projscatter_kernel(
    const int* __restrict__ src, const int* __restrict__ dst,
    int* __restrict__ cur, int* __restrict__ csr, int* __restrict__ bsum,
    const float* __restrict__ feat, const float* __restrict__ W1,
    const float* __restrict__ b1, __half* __restrict__ out,
    float* __restrict__ rn)
{
    __shared__ float sWt[HID][132];       // 33.8 KB, padded
    int tid = threadIdx.x;

    // --- scatter: 2 edges per thread (grid 2048 * 512 = N_EDGES) ---
    {
        int e0 = blockIdx.x * 512 + tid;
        int e1 = e0 + 256;
        int d0 = __ldg(dst + e0), d1 = __ldg(dst + e1);
        int v0 = __ldg(src + e0), v1 = __ldg(src + e1);
        int p0 = atomicAdd(cur + d0, 1);
        int p1 = atomicAdd(cur + d1, 1);
        csr[p0] = v0;
        csr[p1] = v1;
    }
    if (blockIdx.x == 0) bsum[tid] = 0;   // reset chunk sums for next replay

    // --- stage transposed W1 tile ---
    for (int i = tid; i < IN_F * HID; i += 256) {
        int k = i >> 6, j = i & 63;
        sWt[j][k] = W1[i];
    }
    __syncthreads();

    int row0 = blockIdx.x * 32;
    int r8 = tid >> 5, c = tid & 31;
    const float4* fr0 = (const float4*)(feat + (row0 + r8     ) * IN_F);
    const float4* fr1 = (const float4*)(feat + (row0 + r8 +  8) * IN_F);
    const float4* fr2 = (const float4*)(feat + (row0 + r8 + 16) * IN_F);
    const float4* fr3 = (const float4*)(feat + (row0 + r8 + 24) * IN_F);
    float bc0 = b1[c], bc1 = b1[c + 32];
    float a00 = bc0, a01 = bc1, a10 = bc0, a11 = bc1;
    float a20 = bc0, a21 = bc1, a30 = bc0, a31 = bc1;
#pragma unroll
    for (int k4 = 0; k4 < IN_F / 4; k4++) {
        float4 w0 = *(const float4*)&sWt[c     ][k4 * 4];
        float4 w1 = *(const float4*)&sWt[c + 32][k4 * 4];
        float4 f0 = __ldg(fr0 + k4);
        float4 f1 = __ldg(fr1 + k4);
        float4 f2 = __ldg(fr2 + k4);
        float4 f3 = __ldg(fr3 + k4);
        a00 = fmaf(f0.x, w0.x, a00); a00 = fmaf(f0.y, w0.y, a00);
        a00 = fmaf(f0.z, w0.z, a00); a00 = fmaf(f0.w, w0.w, a00);
        a01 = fmaf(f0.x, w1.x, a01); a01 = fmaf(f0.y, w1.y, a01);
        a01 = fmaf(f0.z, w1.z, a01); a01 = fmaf(f0.w, w1.w, a01);
        a10 = fmaf(f1.x, w0.x, a10); a10 = fmaf(f1.y, w0.y, a10);
        a10 = fmaf(f1.z, w0.z, a10); a10 = fmaf(f1.w, w0.w, a10);
        a11 = fmaf(f1.x, w1.x, a11); a11 = fmaf(f1.y, w1.y, a11);
        a11 = fmaf(f1.z, w1.z, a11); a11 = fmaf(f1.w, w1.w, a11);
        a20 = fmaf(f2.x, w0.x, a20); a20 = fmaf(f2.y, w0.y, a20);
        a20 = fmaf(f2.z, w0.z, a20); a20 = fmaf(f2.w, w0.w, a20);
        a21 = fmaf(f2.x, w1.x, a21); a21 = fmaf(f2.y, w1.y, a21);
        a21 = fmaf(f2.z, w1.z, a21); a21 = fmaf(f2.w, w1.w, a21);
        a30 = fmaf(f3.x, w0.x, a30); a30 = fmaf(f3.y, w0.y, a30);
        a30 = fmaf(f3.z, w0.z, a30); a30 = fmaf(f3.w, w0.w, a30);
        a31 = fmaf(f3.x, w1.x, a31); a31 = fmaf(f3.y, w1.y, a31);
        a31 = fmaf(f3.z, w1.z, a31); a31 = fmaf(f3.w, w1.w, a31);
    }
    a00 = fmaxf(a00, 0.0f); a01 = fmaxf(a01, 0.0f);
    a10 = fmaxf(a10, 0.0f); a11 = fmaxf(a11, 0.0f);
    a20 = fmaxf(a20, 0.0f); a21 = fmaxf(a21, 0.0f);
    a30 = fmaxf(a30, 0.0f); a31 = fmaxf(a31, 0.0f);
    out[(row0 + r8     ) * HID + c     ] = __float2half_rn(a00);
    out[(row0 + r8     ) * HID + c + 32] = __float2half_rn(a01);
    out[(row0 + r8 +  8) * HID + c     ] = __float2half_rn(a10);
    out[(row0 + r8 +  8) * HID + c + 32] = __float2half_rn(a11);
    out[(row0 + r8 + 16) * HID + c     ] = __float2half_rn(a20);
    out[(row0 + r8 + 16) * HID + c + 32] = __float2half_rn(a21);
    out[(row0 + r8 + 24) * HID + c     ] = __float2half_rn(a30);
    out[(row0 + r8 + 24) * HID + c + 32] = __float2half_rn(a31);
    float p0 = a00 * a00 + a01 * a01;
    float p1 = a10 * a10 + a11 * a11;
    float p2 = a20 * a20 + a21 * a21;
    float p3 = a30 * a30 + a31 * a31;
#pragma unroll
    for (int o = 16; o; o >>= 1) {
        p0 += __shfl_xor_sync(0xffffffffu, p0, o);
        p1 += __shfl_xor_sync(0xffffffffu, p1, o);
        p2 += __shfl_xor_sync(0xffffffffu, p2, o);
        p3 += __shfl_xor_sync(0xffffffffu, p3, o);
    }
    if (c == 0) {
        rn[row0 + r8     ] = L2E / fmaxf(sqrtf(p0), 1e-12f);
        rn[row0 + r8 +  8] = L2E / fmaxf(sqrtf(p1), 1e-12f);
        rn[row0 + r8 + 16] = L2E / fmaxf(sqrtf(p2), 1e-12f);
        rn[row0 + r8 + 24] = L2E / fmaxf(sqrtf(p3), 1e-12f);
    }
}

// ---------------- launches 4,5: fused AGNN layer (f32x2 math) --------------
// Flat edge loop, per-quarter direct loads, 3 named pipeline slots at 4-edge
// granularity; dot and accumulate in packed f32x2 (FFMA2) -> ~25% fewer instr.
#define PREF(E, SN, RS, RAW)                                              \
    {                                                                     \
        int cidx = min(E, s1m1);                                          \
        SN = __ldg(csr + cidx);                                           \
        RS = __ldg(rn_in + SN);                                           \
        RAW = *(const uint4*)(hh + SN * HID + sub * 8);                   \
    }
#define BODY(E, SN, RS, RAW)                                              \
    {                                                                     \
        unsigned long long f0 = h2f2(RAW.x), f1 = h2f2(RAW.y);            \
        unsigned long long f2 = h2f2(RAW.z), f3 = h2f2(RAW.w);            \
        unsigned long long d2;                                            \
        MUL2(d2, q2[0], f0);                                              \
        FMA2(d2, q2[1], f1, d2);                                          \
        FMA2(d2, q2[2], f2, d2);                                          \
        FMA2(d2, q2[3], f3, d2);                                          \
        float dlo, dhi;                                                   \
        unpk2(d2, dlo, dhi);                                              \
        float dt = dlo + dhi;                                             \
        dt += __shfl_xor_sync(FULL, dt, 1);                               \
        dt += __shfl_xor_sync(FULL, dt, 2);                               \
        dt += __shfl_xor_sync(FULL, dt, 4);                               \
        float w = ex2f(fmaf(dt, RS, mB2));                                \
        w = (E < s1) ? w : 0.0f;                                          \
        ss += w;                                                          \
        unsigned long long w2;                                            \
        asm("mov.b64 %0, {%1, %1};" : "=l"(w2) : "r"(__float_as_uint(w)));\
        FMA2(a2[0], w2, f0, a2[0]);                                       \
        FMA2(a2[1], w2, f1, a2[1]);                                       \
        FMA2(a2[2], w2, f2, a2[2]);                                       \
        FMA2(a2[3], w2, f3, a2[3]);                                       \
        E += 12;                                                          \
        PREF(E, SN, RS, RAW)                                              \
    }

__global__ __launch_bounds__(256) void layer_kernel(
    const int* __restrict__ csr, const int* __restrict__ off,
    const __half* __restrict__ hh, const float* __restrict__ rn_in,
    const float* __restrict__ betas, int layer,
    __half* __restrict__ out_h, float* __restrict__ rn_out)
{
    int node = (blockIdx.x * blockDim.x + threadIdx.x) >> 5;
    int lane = threadIdx.x & 31;
    int qtr  = lane >> 3;
    int sub  = lane & 7;
    const unsigned FULL = 0xffffffffu;

    int s0 = off[node], s1 = off[node + 1];
    int deg = s1 - s0;
    int s1m1 = s1 - 1;
    float beta = __ldg(betas + layer);
    float mB2 = -fabsf(beta) * L2E;               // -log2e * max logit
    unsigned long long q2[4];
    {
        uint4 qraw = *(const uint4*)(hh + node * HID + sub * 8);
        float qs = beta * rn_in[node] * LN2;      // undo the log2e pre-scale
        unsigned long long qs2;
        asm("mov.b64 %0, {%1, %1};" : "=l"(qs2) : "r"(__float_as_uint(qs)));
        q2[0] = h2f2(qraw.x); MUL2(q2[0], q2[0], qs2);
        q2[1] = h2f2(qraw.y); MUL2(q2[1], q2[1], qs2);
        q2[2] = h2f2(qraw.z); MUL2(q2[2], q2[2], qs2);
        q2[3] = h2f2(qraw.w); MUL2(q2[3], q2[3], qs2);
    }

    float ss = 0.0f;
    unsigned long long a2[4] = {0ull, 0ull, 0ull, 0ull};  // packed (0.f, 0.f)

    if (deg > 0) {
        int eA = s0 + qtr, eB = eA + 4, eC = eA + 8;
        int snA, snB, snC; float rsA, rsB, rsC; uint4 rawA, rawB, rawC;
        PREF(eA, snA, rsA, rawA)
        PREF(eB, snB, rsB, rawB)
        PREF(eC, snC, rsC, rawC)
        int nIter = (deg + 3) >> 2;               // 4-edge chunks
        while (nIter >= 3) {
            BODY(eA, snA, rsA, rawA)
            BODY(eB, snB, rsB, rawB)
            BODY(eC, snC, rsC, rawC)
            nIter -= 3;
        }
        if (nIter >= 1) { BODY(eA, snA, rsA, rawA) }
        if (nIter == 2) { BODY(eB, snB, rsB, rawB) }
    }
    // unpack accumulators, combine the 4 quarters
    float acc[8];
    unpk2(a2[0], acc[0], acc[1]);
    unpk2(a2[1], acc[2], acc[3]);
    unpk2(a2[2], acc[4], acc[5]);
    unpk2(a2[3], acc[6], acc[7]);
#pragma unroll
    for (int i = 0; i < 8; i++) {
        acc[i] += __shfl_xor_sync(FULL, acc[i], 8);
        acc[i] += __shfl_xor_sync(FULL, acc[i], 16);
    }
    ss += __shfl_xor_sync(FULL, ss, 8);
    ss += __shfl_xor_sync(FULL, ss, 16);
    float inv = (deg > 0) ? __frcp_rn(ss) : 0.0f;
    float ns = 0.0f;
#pragma unroll
    for (int i = 0; i < 8; i++) {
        acc[i] *= inv;
        ns = fmaf(acc[i], acc[i], ns);
    }
    ns += __shfl_xor_sync(FULL, ns, 1);
    ns += __shfl_xor_sync(FULL, ns, 2);
    ns += __shfl_xor_sync(FULL, ns, 4);
    if (qtr == 0) {
        uint4 r;
        __half2 p;
        p = __floats2half2_rn(acc[0], acc[1]); r.x = *reinterpret_cast<unsigned*>(&p);
        p = __floats2half2_rn(acc[2], acc[3]); r.y = *reinterpret_cast<unsigned*>(&p);
        p = __floats2half2_rn(acc[4], acc[5]); r.z = *reinterpret_cast<unsigned*>(&p);
        p = __floats2half2_rn(acc[6], acc[7]); r.w = *reinterpret_cast<unsigned*>(&p);
        *(uint4*)(out_h + node * HID + sub * 8) = r;
        if (sub == 0)
            rn_out[node] = L2E / fmaxf(sqrtf(ns), 1e-12f);
    }
}

// ---------------- launch 6: cls = h(fp16) @ W2 + b2, 32 rows/block ---------
__global__ __launch_bounds__(256) void cls_kernel(
    const __half* __restrict__ hh, const float* __restrict__ W2,
    const float* __restrict__ b2, float* __restrict__ out)
{
    __shared__ float sF[32][HID];         // 8 KB
    __shared__ float sWt[HID][68];        // 17.4 KB, padded
    int tid = threadIdx.x;
    int row0 = blockIdx.x * 32;
    for (int i = tid; i < 32 * HID; i += 256)
        sF[i >> 6][i & 63] = __half2float(hh[row0 * HID + i]);
    for (int i = tid; i < HID * HID; i += 256) {
        int k = i >> 6, j = i & 63;
        sWt[j][k] = W2[i];
    }
    __syncthreads();

    int r8 = tid >> 5, c = tid & 31;
    float bc0 = b2[c], bc1 = b2[c + 32];
    float a00 = bc0, a01 = bc1, a10 = bc0, a11 = bc1;
    float a20 = bc0, a21 = bc1, a30 = bc0, a31 = bc1;
#pragma unroll
    for (int k4 = 0; k4 < HID / 4; k4++) {
        float4 w0 = *(const float4*)&sWt[c     ][k4 * 4];
        float4 w1 = *(const float4*)&sWt[c + 32][k4 * 4];
        float4 f0 = *(const float4*)&sF[r8     ][k4 * 4];
        float4 f1 = *(const float4*)&sF[r8 +  8][k4 * 4];
        float4 f2 = *(const float4*)&sF[r8 + 16][k4 * 4];
        float4 f3 = *(const float4*)&sF[r8 + 24][k4 * 4];
        a00 = fmaf(f0.x, w0.x, a00); a00 = fmaf(f0.y, w0.y, a00);
        a00 = fmaf(f0.z, w0.z, a00); a00 = fmaf(f0.w, w0.w, a00);
        a01 = fmaf(f0.x, w1.x, a01); a01 = fmaf(f0.y, w1.y, a01);
        a01 = fmaf(f0.z, w1.z, a01); a01 = fmaf(f0.w, w1.w, a01);
        a10 = fmaf(f1.x, w0.x, a10); a10 = fmaf(f1.y, w0.y, a10);
        a10 = fmaf(f1.z, w0.z, a10); a10 = fmaf(f1.w, w0.w, a10);
        a11 = fmaf(f1.x, w1.x, a11); a11 = fmaf(f1.y, w1.y, a11);
        a11 = fmaf(f1.z, w1.z, a11); a11 = fmaf(f1.w, w1.w, a11);
        a20 = fmaf(f2.x, w0.x, a20); a20 = fmaf(f2.y, w0.y, a20);
        a20 = fmaf(f2.z, w0.z, a20); a20 = fmaf(f2.w, w0.w, a20);
        a21 = fmaf(f2.x, w1.x, a21); a21 = fmaf(f2.y, w1.y, a21);
        a21 = fmaf(f2.z, w1.z, a21); a21 = fmaf(f2.w, w1.w, a21);
        a30 = fmaf(f3.x, w0.x, a30); a30 = fmaf(f3.y, w0.y, a30);
        a30 = fmaf(f3.z, w0.z, a30); a30 = fmaf(f3.w, w0.w, a30);
        a31 = fmaf(f3.x, w1.x, a31); a31 = fmaf(f3.y, w1.y, a31);
        a31 = fmaf(f3.z, w1.z, a31); a31 = fmaf(f3.w, w1.w, a31);
    }
    out[(row0 + r8     ) * HID + c     ] = a00;
    out[(row0 + r8     ) * HID + c + 32] = a01;
    out[(row0 + r8 +  8) * HID + c     ] = a10;
    out[(row0 + r8 +  8) * HID + c + 32] = a11;
    out[(row0 + r8 + 16) * HID + c     ] = a20;
    out[(row0 + r8 + 16) * HID + c + 32] = a21;
    out[(row0 + r8 + 24) * HID + c     ] = a30;
    out[(row0 + r8 + 24) * HID + c + 32] = a31;
}

// ---------------------------------------------------------------------------
extern "C" void kernel_launch(void* const* d_in, const int* in_sizes, int n_in,
                              void* d_out, int out_size)
{
    const float* feat  = (const float*)d_in[0];
    const int*   src   = (const int*)  d_in[1];
    const int*   dst   = (const int*)  d_in[2];
    const float* W1    = (const float*)d_in[3];
    const float* b1    = (const float*)d_in[4];
    const float* W2    = (const float*)d_in[5];
    const float* b2    = (const float*)d_in[6];
    const float* betas = (const float*)d_in[7];

    __half *h0, *h1; float *rnA, *rnB; int *deg, *off, *cur, *bsum, *csr;
    cudaGetSymbolAddress((void**)&h0,   g_h0);
    cudaGetSymbolAddress((void**)&h1,   g_h1);
    cudaGetSymbolAddress((void**)&rnA,  g_rnA);
    cudaGetSymbolAddress((void**)&rnB,  g_rnB);
    cudaGetSymbolAddress((void**)&deg,  g_deg);
    cudaGetSymbolAddress((void**)&off,  g_off);
    cudaGetSymbolAddress((void**)&cur,  g_cur);
    cudaGetSymbolAddress((void**)&bsum, g_bsum);
    cudaGetSymbolAddress((void**)&csr,  g_csr);

    hist_kernel<<<N_EDGES / 8 / 256, 256>>>(dst, deg, bsum);
    scanF_kernel<<<N_NODES / 256, 256>>>(bsum, deg, off, cur);
    projscatter_kernel<<<N_NODES / 32, 256>>>(src, dst, cur, csr, bsum,
                                              feat, W1, b1, h0, rnA);
    layer_kernel<<<N_NODES * 32 / 256, 256>>>(csr, off, h0, rnA, betas, 0, h1, rnB);
    layer_kernel<<<N_NODES * 32 / 256, 256>>>(csr, off, h1, rnB, betas, 1, h0, rnA);
    cls_kernel<<<N_NODES / 32, 256>>>(h0, W2, b2, (float*)d_out);
}